// round 14
// baseline (speedup 1.0000x reference)
#include <cuda_runtime.h>
#include <cuda_fp16.h>
#include <math.h>
#include <stdint.h>

// Problem constants
#define BATCH 8
#define CH    192
#define QKVC  576
#define HW    16384
#define HEADS 4
#define CPH   48

// ---------------- scratch (static device memory; no allocs) ----------------
__device__ uint4 g_q0h[(size_t)BATCH * QKVC * HW * 2 / 16];   // fp16 qkv after 1x1 (planar)
__device__ uint4 g_q1h[(size_t)BATCH * QKVC * HW * 2 / 16];   // fp16 qkv after dw (planar)
__device__ float g_sumsq[BATCH * 2 * CH];
__device__ float g_S[BATCH * HEADS * CPH * CPH];
__device__ float g_masksum[BATCH];
__device__ uint4 g_xh4[(size_t)BATCH * CH * HW * 2 / 16];     // [B][192][HW] fp16 planar
__device__ uint4 g_wb4[(size_t)(QKVC + 64) * CH * 2 / 16];    // [576(+pad)][192] fp16
__device__ uint4 g_weff[(size_t)BATCH * 256 * CH * 2 / 16];   // [B][192(+pad)][192] fp16

// ---------------- helpers ----------------
__device__ __forceinline__ uint32_t smem_u32(const void* p) {
    uint32_t a;
    asm("{ .reg .u64 t; cvta.to.shared.u64 t, %1; cvt.u32.u64 %0, t; }" : "=r"(a) : "l"(p));
    return a;
}
#define SWZ(off) ((off) ^ (((off) >> 3) & 0x70))

__device__ __forceinline__ void cp16(uint32_t dst, const void* src, int srcsz) {
    asm volatile("cp.async.cg.shared.global [%0], [%1], 16, %2;"
                 :: "r"(dst), "l"(src), "r"(srcsz) : "memory");
}
#define CP_COMMIT() asm volatile("cp.async.commit_group;" ::: "memory")

#define LDSM4(r0, r1, r2, r3, addr)                                            \
    asm volatile("ldmatrix.sync.aligned.m8n8.x4.shared.b16 {%0,%1,%2,%3}, [%4];" \
                 : "=r"(r0), "=r"(r1), "=r"(r2), "=r"(r3) : "r"(addr))

#define LDSM4T(r0, r1, r2, r3, addr)                                           \
    asm volatile("ldmatrix.sync.aligned.m8n8.x4.trans.shared.b16 {%0,%1,%2,%3}, [%4];" \
                 : "=r"(r0), "=r"(r1), "=r"(r2), "=r"(r3) : "r"(addr))

#define MMA16816(c, a, b0, b1)                                                 \
    asm volatile("mma.sync.aligned.m16n8k16.row.col.f32.f16.f16.f32 "          \
                 "{%0,%1,%2,%3},{%4,%5,%6,%7},{%8,%9},{%0,%1,%2,%3};"          \
                 : "+f"((c)[0]), "+f"((c)[1]), "+f"((c)[2]), "+f"((c)[3])      \
                 : "r"((a)[0]), "r"((a)[1]), "r"((a)[2]), "r"((a)[3]),         \
                   "r"(b0), "r"(b1))

__device__ __forceinline__ void h8_to_f2(const uint4 v, float4* lo, float4* hi) {
    const __half2* h2 = (const __half2*)&v;
    float2 a = __half22float2(h2[0]);
    float2 b = __half22float2(h2[1]);
    float2 c = __half22float2(h2[2]);
    float2 d = __half22float2(h2[3]);
    *lo = make_float4(a.x, a.y, b.x, b.y);
    *hi = make_float4(c.x, c.y, d.x, d.y);
}

// ---------------- setup: mask sums, zeroing, weight convert, x fp32->fp16 --
__global__ void __launch_bounds__(256) setup_kernel(const float* __restrict__ mask,
                                                    const float* __restrict__ qkvw,
                                                    __half* __restrict__ Wb,
                                                    const float* __restrict__ X,
                                                    __half* __restrict__ Xh) {
    const int bid = blockIdx.x, t = threadIdx.x;
    if (bid >= 648) {
        const size_t total4 = (size_t)BATCH * CH * HW / 4;
        for (size_t i = (size_t)(bid - 648) * 256 + t; i < total4; i += (size_t)6144 * 256) {
            float4 v = ((const float4*)X)[i];
            __half2 lo = __floats2half2_rn(v.x, v.y);
            __half2 hi = __floats2half2_rn(v.z, v.w);
            uint2 o;
            o.x = *(uint32_t*)&lo;
            o.y = *(uint32_t*)&hi;
            ((uint2*)Xh)[i] = o;
        }
    } else if (bid < 8) {
        const int b = bid;
        const float4* m4 = (const float4*)(mask + (size_t)b * HW);
        float s = 0.f;
        for (int i = t; i < HW / 4; i += 256) {
            float4 v = m4[i];
            s += v.x + v.y + v.z + v.w;
        }
#pragma unroll
        for (int o = 16; o > 0; o >>= 1) s += __shfl_xor_sync(0xFFFFFFFFu, s, o);
        __shared__ float red[8];
        if ((t & 31) == 0) red[t >> 5] = s;
        __syncthreads();
        if (t == 0) {
            float tot = 0.f;
#pragma unroll
            for (int i = 0; i < 8; i++) tot += red[i];
            g_masksum[b] = tot;
        }
    } else if (bid < 72) {
        const int idx = (bid - 8) * 256 + t;
        for (int i = idx; i < BATCH * HEADS * CPH * CPH; i += 64 * 256) g_S[i] = 0.f;
        for (int i = idx; i < BATCH * 2 * CH; i += 64 * 256) g_sumsq[i] = 0.f;
    } else {
        const int m = bid - 72;
        if (t < CH)
            Wb[(size_t)m * CH + t] = __float2half_rn(qkvw[(size_t)m * CH + t]);
    }
}

// ---------------- multi-tile planar-B fp16 GEMM via mma.sync ---------------
// Each CTA keeps A (128m x 192k) resident and sweeps NT n-tiles of 128 pixels.
// Chunk stream: cc = 0..3*NT-1; chunk cc covers A-chunk cc%3, n-tile cc/3.
#define VB_ROW 272
#define VB_BYTES (64 * VB_ROW)
#define SM_VB (3 * 16384)
#define SMEM_GEMM (1024 + SM_VB + 2 * VB_BYTES)

template <typename OT, bool SCALE, bool ABATCH, int NT>
__global__ void __launch_bounds__(256, 2)
gemm_planar(const __half* __restrict__ Ball, const __half* __restrict__ A,
            const float* __restrict__ bias, OT* __restrict__ Y, int Mtot,
            int chanPB, int chanOff,
            const float* __restrict__ mask, const float* __restrict__ tbp) {
    extern __shared__ __align__(16) char smraw[];
    uint32_t sbr = smem_u32(smraw);
    uint32_t sb = (sbr + 1023) & ~1023u;
    const int t = threadIdx.x;
    const int warp = t >> 5, lane = t & 31;
    const int wm = warp >> 2, wn = warp & 3;      // warp tile m64 x n32
    const int b = blockIdx.z;
    const int M0 = blockIdx.x * 128;
    const int Nbase = blockIdx.y * (128 * NT);
    const __half* vbase = Ball + (size_t)(b * chanPB + chanOff) * HW;
    const __half* Ab = A + (ABATCH ? (size_t)b * 256 * CH : 0);
    const int g = lane >> 2, tg = lane & 3;

    // A: 3 chunks (48KB), resident for all NT tiles (grouped with chunk 0)
#pragma unroll
    for (int i = 0; i < 12; i++) {
        int u = t + i * 256;
        int ca = u >> 10, v = u & 1023;
        int row = v >> 3, q = v & 7;
        const void* src = Ab + (size_t)(M0 + row) * CH + ca * 64 + q * 8;
        cp16(sb + ca * 16384 + SWZ(row * 128 + q * 16), src,
             (M0 + row < Mtot) ? 16 : 0);
    }
    // chunk loader: chunk index cc -> buffer cc&1, A-chunk cc%3, n-tile cc/3
#define VB_LOAD(cc) do {                                                           \
        const int _ca = (cc) % 3, _nt = (cc) / 3;                                  \
        uint32_t _dst = sb + SM_VB + (uint32_t)((cc) & 1) * VB_BYTES;              \
        const __half* _vb = vbase + (size_t)(_ca * 64) * HW + Nbase + _nt * 128;   \
        _Pragma("unroll")                                                          \
        for (int _i = 0; _i < 4; _i++) {                                           \
            int _u = t + _i * 256;                                                 \
            int _kr = _u >> 4, _q = _u & 15;                                       \
            cp16(_dst + _kr * VB_ROW + _q * 16,                                    \
                 _vb + (size_t)_kr * HW + _q * 8, 16);                             \
        }                                                                          \
        CP_COMMIT();                                                               \
    } while (0)

    VB_LOAD(0);
    VB_LOAD(1);

    // hoist bias (m indices fixed for the whole CTA)
    float bsr[4][2];
#pragma unroll
    for (int mf = 0; mf < 4; mf++)
#pragma unroll
        for (int half = 0; half < 2; half++) {
            int m = M0 + wm * 64 + mf * 16 + g + half * 8;
            bsr[mf][half] = (m < Mtot) ? bias[m] : 0.f;
        }

    float acc[4][4][4];
#pragma unroll
    for (int i = 0; i < 4; i++)
#pragma unroll
        for (int j = 0; j < 4; j++)
#pragma unroll
            for (int k = 0; k < 4; k++) acc[i][j][k] = 0.f;

    const int TC = 3 * NT;
#pragma unroll 1
    for (int cc = 0; cc < TC; cc++) {
        if (cc < TC - 1) asm volatile("cp.async.wait_group 1;" ::: "memory");
        else             asm volatile("cp.async.wait_group 0;" ::: "memory");
        __syncthreads();

        const uint32_t abuf = sb + (uint32_t)(cc % 3) * 16384;
        const uint32_t vbuf = sb + SM_VB + (uint32_t)(cc & 1) * VB_BYTES;
#pragma unroll
        for (int kk = 0; kk < 4; kk++) {
            uint32_t af[4][4];
#pragma unroll
            for (int mf = 0; mf < 4; mf++) {
                int row = wm * 64 + mf * 16 + (lane & 7) + ((lane & 8) ? 8 : 0);
                int cb = kk * 32 + ((lane & 16) ? 16 : 0);
                LDSM4(af[mf][0], af[mf][1], af[mf][2], af[mf][3],
                      abuf + SWZ(row * 128 + cb));
            }
#pragma unroll
            for (int nf2 = 0; nf2 < 2; nf2++) {
                int krow = kk * 16 + (lane & 7) + ((lane & 8) ? 8 : 0);
                int ncol = wn * 32 + nf2 * 16 + ((lane & 16) ? 8 : 0);
                uint32_t b0, b1, b2, b3;
                LDSM4T(b0, b1, b2, b3, vbuf + krow * VB_ROW + ncol * 2);
#pragma unroll
                for (int mf = 0; mf < 4; mf++) {
                    MMA16816(acc[mf][nf2 * 2 + 0], af[mf], b0, b1);
                    MMA16816(acc[mf][nf2 * 2 + 1], af[mf], b2, b3);
                }
            }
        }
        __syncthreads();
        if (cc + 2 < TC) VB_LOAD(cc + 2);   // async; overlaps epilogue below

        if (cc % 3 == 2) {
            // epilogue for n-tile cc/3
            const int N0 = Nbase + (cc / 3) * 128;
            const int nbase = N0 + wn * 32 + tg * 2;
            float2 sp[4];
            if (SCALE) {
                const float tb = fminf(fmaxf(*tbp, 0.1f), 0.5f);
                const float* mrow = mask + (size_t)b * HW;
#pragma unroll
                for (int nf = 0; nf < 4; nf++) {
                    sp[nf].x = 1.f + tb * mrow[nbase + nf * 8];
                    sp[nf].y = 1.f + tb * mrow[nbase + nf * 8 + 1];
                }
            }
#pragma unroll
            for (int mf = 0; mf < 4; mf++) {
#pragma unroll
                for (int half = 0; half < 2; half++) {
                    int m = M0 + wm * 64 + mf * 16 + g + half * 8;
                    if (m < Mtot) {
                        float bs = bsr[mf][half];
                        OT* yrow = Y + ((size_t)b * Mtot + m) * HW + nbase;
#pragma unroll
                        for (int nf = 0; nf < 4; nf++) {
                            float v0 = acc[mf][nf][half * 2 + 0];
                            float v1 = acc[mf][nf][half * 2 + 1];
                            if (SCALE) { v0 = v0 * sp[nf].x; v1 = v1 * sp[nf].y; }
                            v0 += bs; v1 += bs;
                            if constexpr (sizeof(OT) == 4)
                                *(float2*)(yrow + nf * 8) = make_float2(v0, v1);
                            else
                                *(__half2*)(yrow + nf * 8) = __floats2half2_rn(v0, v1);
                        }
                    }
                }
            }
#pragma unroll
            for (int i = 0; i < 4; i++)
#pragma unroll
                for (int j = 0; j < 4; j++)
#pragma unroll
                    for (int k = 0; k < 4; k++) acc[i][j][k] = 0.f;
        }
    }
#undef VB_LOAD
}

// ---------------- 3x3 depthwise conv (groups=576), 32-row tiles, fp16 in/out
__global__ void __launch_bounds__(256) dwconv_kernel(const __half* __restrict__ in,
                                                     const float* __restrict__ w,
                                                     const float* __restrict__ bias,
                                                     __half* __restrict__ out) {
    const int b = blockIdx.z, ch = blockIdx.y;
    const int t = threadIdx.x;
    const int r0 = blockIdx.x * 32;
    __shared__ __align__(16) float sm[34][132];
    const __half* src = in + ((size_t)b * QKVC + ch) * HW;

#pragma unroll
    for (int i = 0; i < 3; i++) {
        int idx = t + i * 256;
        if (idx < 544) {
            int rr = idx >> 4, c8 = (idx & 15) * 8;
            int gr = r0 - 1 + rr;
            float4 lo = make_float4(0, 0, 0, 0), hi = lo;
            if (gr >= 0 && gr < 128) {
                uint4 v = *(const uint4*)(src + gr * 128 + c8);
                h8_to_f2(v, &lo, &hi);
            }
            *(float4*)&sm[rr][c8] = lo;
            *(float4*)&sm[rr][c8 + 4] = hi;
        }
    }
    float wv[9];
#pragma unroll
    for (int i = 0; i < 9; i++) wv[i] = w[ch * 9 + i];
    const float bsv = bias[ch];
    __syncthreads();

    const int lr = (t >> 4) * 2;
    const int xo = (t & 15) * 8;
    float R[4][16];
#pragma unroll
    for (int dy = 0; dy < 4; dy++) {
        const float* row = sm[lr + dy];
        float4 v;
        v = (xo > 0) ? *(const float4*)(row + xo - 4) : make_float4(0, 0, 0, 0);
        R[dy][0] = v.x; R[dy][1] = v.y; R[dy][2] = v.z; R[dy][3] = v.w;
        v = *(const float4*)(row + xo);
        R[dy][4] = v.x; R[dy][5] = v.y; R[dy][6] = v.z; R[dy][7] = v.w;
        v = *(const float4*)(row + xo + 4);
        R[dy][8] = v.x; R[dy][9] = v.y; R[dy][10] = v.z; R[dy][11] = v.w;
        v = (xo < 120) ? *(const float4*)(row + xo + 8) : make_float4(0, 0, 0, 0);
        R[dy][12] = v.x; R[dy][13] = v.y; R[dy][14] = v.z; R[dy][15] = v.w;
    }
    float ss = 0.f;
#pragma unroll
    for (int rr2 = 0; rr2 < 2; rr2++) {
        float o[8];
#pragma unroll
        for (int i = 0; i < 8; i++) {
            float a = bsv;
#pragma unroll
            for (int dy = 0; dy < 3; dy++)
                a += wv[dy * 3 + 0] * R[rr2 + dy][3 + i] +
                     wv[dy * 3 + 1] * R[rr2 + dy][4 + i] +
                     wv[dy * 3 + 2] * R[rr2 + dy][5 + i];
            o[i] = a; ss += a * a;
        }
        __align__(16) __half oh[8];
#pragma unroll
        for (int i = 0; i < 8; i++) oh[i] = __float2half_rn(o[i]);
        *(uint4*)(out + ((size_t)b * QKVC + ch) * HW + (r0 + lr + rr2) * 128 + xo) =
            *(const uint4*)oh;
    }

    if (ch < 2 * CH) {
#pragma unroll
        for (int off = 16; off > 0; off >>= 1)
            ss += __shfl_xor_sync(0xFFFFFFFFu, ss, off);
        if ((t & 31) == 0) atomicAdd(&g_sumsq[b * 2 * CH + ch], ss);
    }
}

// ---------------- attention scores via mma.sync: S[bh] += q·k^T (16-way split)
#define ATM_SMEM (1024 + 2 * 16384)

__global__ void __launch_bounds__(256) attn_mma(const __half* __restrict__ qkv) {
    extern __shared__ __align__(16) char atraw[];
    uint32_t sbr = smem_u32(atraw);
    uint32_t sb = (sbr + 1023) & ~1023u;
    const int bh = blockIdx.y, b = bh >> 2, h = bh & 3;
    const int t = threadIdx.x;
    const int warp = t >> 5, lane = t & 31;
    const int wm = warp >> 2, wn = warp & 3;      // warp tile m32 x n16
    const __half* qbase = qkv + ((size_t)b * QKVC + h * CPH) * HW;
    const __half* kbase = qbase + (size_t)CH * HW;
    const int n0 = blockIdx.x * 1024;             // 16 iterations of k64

#define ATM_LOAD(it) do {                                                          \
        const int _nw = n0 + (it) * 64;                                            \
        _Pragma("unroll")                                                          \
        for (int _i = 0; _i < 4; _i++) {                                           \
            int _u = t + _i * 256;                                                 \
            int _isK = _u >= 512;                                                  \
            int _v = _u & 511;                                                     \
            int _row = _v >> 3, _q8 = _v & 7;                                      \
            const __half* _src = (_isK ? kbase : qbase) + (size_t)_row * HW + _nw + _q8 * 8; \
            cp16(sb + (uint32_t)((it) & 1) * 16384 + (_isK ? 8192 : 0) +           \
                     SWZ(_row * 128 + _q8 * 16),                                   \
                 _src, (_row < CPH) ? 16 : 0);                                     \
        }                                                                          \
        CP_COMMIT();                                                               \
    } while (0)

    ATM_LOAD(0);
    ATM_LOAD(1);

    float acc[2][2][4];
#pragma unroll
    for (int i = 0; i < 2; i++)
#pragma unroll
        for (int j = 0; j < 2; j++)
#pragma unroll
            for (int k = 0; k < 4; k++) acc[i][j][k] = 0.f;

    for (int bi = 0; bi < 16; bi++) {
        if (bi < 15) asm volatile("cp.async.wait_group 1;" ::: "memory");
        else         asm volatile("cp.async.wait_group 0;" ::: "memory");
        __syncthreads();
        const uint32_t qbuf = sb + (uint32_t)(bi & 1) * 16384;
        const uint32_t kbuf = qbuf + 8192;
#pragma unroll
        for (int kk = 0; kk < 4; kk++) {
            uint32_t af[2][4];
#pragma unroll
            for (int mf = 0; mf < 2; mf++) {
                int row = wm * 32 + mf * 16 + (lane & 7) + ((lane & 8) ? 8 : 0);
                int cb = kk * 32 + ((lane & 16) ? 16 : 0);
                LDSM4(af[mf][0], af[mf][1], af[mf][2], af[mf][3],
                      qbuf + SWZ(row * 128 + cb));
            }
            int rowb = wn * 16 + (lane & 7) + ((lane & 16) ? 8 : 0);
            int cbb = kk * 32 + ((lane & 8) ? 16 : 0);
            uint32_t b0, b1, b2, b3;
            LDSM4(b0, b1, b2, b3, kbuf + SWZ(rowb * 128 + cbb));
#pragma unroll
            for (int mf = 0; mf < 2; mf++) {
                MMA16816(acc[mf][0], af[mf], b0, b1);
                MMA16816(acc[mf][1], af[mf], b2, b3);
            }
        }
        __syncthreads();
        if (bi + 2 < 16) ATM_LOAD(bi + 2);
    }
#undef ATM_LOAD

    float* Sb = g_S + (size_t)bh * CPH * CPH;
    const int g = lane >> 2, tg = lane & 3;
#pragma unroll
    for (int mf = 0; mf < 2; mf++)
#pragma unroll
        for (int half = 0; half < 2; half++) {
            int m = wm * 32 + mf * 16 + g + half * 8;
            if (m < CPH) {
#pragma unroll
                for (int nf = 0; nf < 2; nf++)
#pragma unroll
                    for (int j = 0; j < 2; j++) {
                        int d = wn * 16 + nf * 8 + tg * 2 + j;
                        if (d < CPH)
                            atomicAdd(&Sb[m * CPH + d], acc[mf][nf][half * 2 + j]);
                    }
            }
        }
}

// ---------------- fused softmax (norm+temp) + Weff = W2 · blockdiag(A) -----
__global__ void __launch_bounds__(192) softmax_weff(const float* __restrict__ det,
                                                    const float* __restrict__ smo,
                                                    const float* __restrict__ W2,
                                                    __half* __restrict__ Weff) {
    const int b = blockIdx.x, t = threadIdx.x;   // 192 threads
    __shared__ float As[HEADS * CPH * CPH];

    {
        const int h = t / CPH, r = t % CPH;
        const float tl = g_masksum[b] / (float)HW;
        const float temp = det[h] * tl + smo[h] * (1.f - tl);
        const float invq = 1.f / fmaxf(sqrtf(g_sumsq[b * 2 * CH + h * CPH + r]), 1e-12f);
        const float* Srow = g_S + ((size_t)(b * HEADS + h) * CPH + r) * CPH;
        float vals[CPH];
        float mx = -1e30f;
#pragma unroll
        for (int d = 0; d < CPH; d++) {
            float invk = 1.f / fmaxf(sqrtf(g_sumsq[b * 2 * CH + CH + h * CPH + d]), 1e-12f);
            float v = Srow[d] * invq * invk * temp;
            vals[d] = v;
            mx = fmaxf(mx, v);
        }
        float sum = 0.f;
#pragma unroll
        for (int d = 0; d < CPH; d++) { vals[d] = expf(vals[d] - mx); sum += vals[d]; }
        float inv = 1.f / sum;
        float* Arow = As + (h * CPH + r) * CPH;
#pragma unroll
        for (int d = 0; d < CPH; d++) Arow[d] = vals[d] * inv;
    }
    __syncthreads();

    const int m = t;
    __half* wrow_out = Weff + ((size_t)b * 256 + m) * CH;
#pragma unroll
    for (int h = 0; h < HEADS; h++) {
        float wr[CPH];
#pragma unroll
        for (int cc = 0; cc < CPH; cc++) wr[cc] = W2[(size_t)m * CH + h * CPH + cc];
        const float* Ah = As + h * CPH * CPH;
        for (int d0 = 0; d0 < CPH; d0 += 4) {
            float s0 = 0.f, s1 = 0.f, s2 = 0.f, s3 = 0.f;
#pragma unroll
            for (int cc = 0; cc < CPH; cc++) {
                float w = wr[cc];
                const float* ar = Ah + cc * CPH + d0;
                s0 += w * ar[0]; s1 += w * ar[1];
                s2 += w * ar[2]; s3 += w * ar[3];
            }
            wrow_out[h * CPH + d0 + 0] = __float2half_rn(s0);
            wrow_out[h * CPH + d0 + 1] = __float2half_rn(s1);
            wrow_out[h * CPH + d0 + 2] = __float2half_rn(s2);
            wrow_out[h * CPH + d0 + 3] = __float2half_rn(s3);
        }
    }
}

// ---------------- host launcher ----------------
extern "C" void kernel_launch(void* const* d_in, const int* in_sizes, int n_in,
                              void* d_out, int out_size) {
    const float* x    = (const float*)d_in[0];
    const float* mask = (const float*)d_in[1];
    const float* qkvw = (const float*)d_in[2];
    const float* qkvb = (const float*)d_in[3];
    const float* dww  = (const float*)d_in[4];
    const float* dwb  = (const float*)d_in[5];
    const float* outw = (const float*)d_in[6];
    const float* outb = (const float*)d_in[7];
    const float* det  = (const float*)d_in[8];
    const float* smo  = (const float*)d_in[9];
    const float* tbp  = (const float*)d_in[10];
    float* y = (float*)d_out;

    void *p_q0 = nullptr, *p_q1 = nullptr, *p_xh = nullptr, *p_wb = nullptr, *p_we = nullptr;
    cudaGetSymbolAddress(&p_q0, g_q0h);
    cudaGetSymbolAddress(&p_q1, g_q1h);
    cudaGetSymbolAddress(&p_xh, g_xh4);
    cudaGetSymbolAddress(&p_wb, g_wb4);
    cudaGetSymbolAddress(&p_we, g_weff);

    auto gemm_qkv = gemm_planar<__half, false, false, 8>;
    auto gemm_out = gemm_planar<float, true, true, 4>;
    cudaFuncSetAttribute(gemm_qkv, cudaFuncAttributeMaxDynamicSharedMemorySize, SMEM_GEMM);
    cudaFuncSetAttribute(gemm_out, cudaFuncAttributeMaxDynamicSharedMemorySize, SMEM_GEMM);
    cudaFuncSetAttribute(attn_mma, cudaFuncAttributeMaxDynamicSharedMemorySize, ATM_SMEM);

    // setup: mask sums + zeroing + weight convert + x fp32->fp16 (one launch)
    setup_kernel<<<648 + 6144, 256>>>(mask, qkvw, (__half*)p_wb, x, (__half*)p_xh);
    // qkv 1x1 conv: multi-tile GEMM (8 n-tiles per CTA, A resident)
    gemm_qkv<<<dim3(5, HW / (128 * 8), BATCH), 256, SMEM_GEMM>>>(
        (const __half*)p_xh, (const __half*)p_wb, qkvb, (__half*)p_q0, QKVC,
        CH, 0, nullptr, nullptr);
    // 3x3 depthwise (+ fused q/k sum-of-squares)
    dwconv_kernel<<<dim3(4, QKVC, BATCH), 256>>>(
        (const __half*)p_q0, dww, dwb, (__half*)p_q1);
    // channel attention scores via tensor cores (16-way split-K)
    attn_mma<<<dim3(16, BATCH * HEADS), 256, ATM_SMEM>>>((const __half*)p_q1);
    // softmax + Weff fold (one launch)
    softmax_weff<<<BATCH, 192>>>(det, smo, outw, (__half*)p_we);
    // y = (Weff @ v) * s(n) + outb : multi-tile GEMM (4 n-tiles per CTA)
    gemm_out<<<dim3(2, HW / (128 * 4), BATCH), 256, SMEM_GEMM>>>(
        (const __half*)p_q1, (const __half*)p_we, outb, y, CH,
        QKVC, 2 * CH, mask, tbp);
}

// round 15
// speedup vs baseline: 1.0613x; 1.0613x over previous
#include <cuda_runtime.h>
#include <cuda_fp16.h>
#include <math.h>
#include <stdint.h>

// Problem constants
#define BATCH 8
#define CH    192
#define QKVC  576
#define HW    16384
#define HEADS 4
#define CPH   48

// ---------------- scratch (static device memory; no allocs) ----------------
__device__ uint4 g_q0h[(size_t)BATCH * QKVC * HW * 2 / 16];   // fp16 qkv after 1x1 (planar)
__device__ uint4 g_q1h[(size_t)BATCH * QKVC * HW * 2 / 16];   // fp16 qkv after dw (planar)
__device__ float g_sumsq[BATCH * 2 * CH];
__device__ float g_S[BATCH * HEADS * CPH * CPH];
__device__ float g_masksum[BATCH];
__device__ uint4 g_xh4[(size_t)BATCH * CH * HW * 2 / 16];     // [B][192][HW] fp16 planar
__device__ uint4 g_wb4[(size_t)(QKVC + 64) * CH * 2 / 16];    // [576(+pad)][192] fp16
__device__ uint4 g_weff[(size_t)BATCH * 256 * CH * 2 / 16];   // [B][192(+pad)][192] fp16

// ---------------- helpers ----------------
__device__ __forceinline__ uint32_t smem_u32(const void* p) {
    uint32_t a;
    asm("{ .reg .u64 t; cvta.to.shared.u64 t, %1; cvt.u32.u64 %0, t; }" : "=r"(a) : "l"(p));
    return a;
}
#define SWZ(off) ((off) ^ (((off) >> 3) & 0x70))

__device__ __forceinline__ void cp16(uint32_t dst, const void* src, int srcsz) {
    asm volatile("cp.async.cg.shared.global [%0], [%1], 16, %2;"
                 :: "r"(dst), "l"(src), "r"(srcsz) : "memory");
}
#define CP_COMMIT() asm volatile("cp.async.commit_group;" ::: "memory")

#define LDSM4(r0, r1, r2, r3, addr)                                            \
    asm volatile("ldmatrix.sync.aligned.m8n8.x4.shared.b16 {%0,%1,%2,%3}, [%4];" \
                 : "=r"(r0), "=r"(r1), "=r"(r2), "=r"(r3) : "r"(addr))

#define LDSM4T(r0, r1, r2, r3, addr)                                           \
    asm volatile("ldmatrix.sync.aligned.m8n8.x4.trans.shared.b16 {%0,%1,%2,%3}, [%4];" \
                 : "=r"(r0), "=r"(r1), "=r"(r2), "=r"(r3) : "r"(addr))

#define MMA16816(c, a, b0, b1)                                                 \
    asm volatile("mma.sync.aligned.m16n8k16.row.col.f32.f16.f16.f32 "          \
                 "{%0,%1,%2,%3},{%4,%5,%6,%7},{%8,%9},{%0,%1,%2,%3};"          \
                 : "+f"((c)[0]), "+f"((c)[1]), "+f"((c)[2]), "+f"((c)[3])      \
                 : "r"((a)[0]), "r"((a)[1]), "r"((a)[2]), "r"((a)[3]),         \
                   "r"(b0), "r"(b1))

__device__ __forceinline__ void h8_to_f2(const uint4 v, float4* lo, float4* hi) {
    const __half2* h2 = (const __half2*)&v;
    float2 a = __half22float2(h2[0]);
    float2 b = __half22float2(h2[1]);
    float2 c = __half22float2(h2[2]);
    float2 d = __half22float2(h2[3]);
    *lo = make_float4(a.x, a.y, b.x, b.y);
    *hi = make_float4(c.x, c.y, d.x, d.y);
}

// ---------------- setup: mask sums, zeroing, weight convert, x fp32->fp16 --
__global__ void __launch_bounds__(256) setup_kernel(const float* __restrict__ mask,
                                                    const float* __restrict__ qkvw,
                                                    __half* __restrict__ Wb,
                                                    const float* __restrict__ X,
                                                    __half* __restrict__ Xh) {
    const int bid = blockIdx.x, t = threadIdx.x;
    if (bid >= 648) {
        const size_t total4 = (size_t)BATCH * CH * HW / 4;
        for (size_t i = (size_t)(bid - 648) * 256 + t; i < total4; i += (size_t)6144 * 256) {
            float4 v = ((const float4*)X)[i];
            __half2 lo = __floats2half2_rn(v.x, v.y);
            __half2 hi = __floats2half2_rn(v.z, v.w);
            uint2 o;
            o.x = *(uint32_t*)&lo;
            o.y = *(uint32_t*)&hi;
            ((uint2*)Xh)[i] = o;
        }
    } else if (bid < 8) {
        const int b = bid;
        const float4* m4 = (const float4*)(mask + (size_t)b * HW);
        float s = 0.f;
        for (int i = t; i < HW / 4; i += 256) {
            float4 v = m4[i];
            s += v.x + v.y + v.z + v.w;
        }
#pragma unroll
        for (int o = 16; o > 0; o >>= 1) s += __shfl_xor_sync(0xFFFFFFFFu, s, o);
        __shared__ float red[8];
        if ((t & 31) == 0) red[t >> 5] = s;
        __syncthreads();
        if (t == 0) {
            float tot = 0.f;
#pragma unroll
            for (int i = 0; i < 8; i++) tot += red[i];
            g_masksum[b] = tot;
        }
    } else if (bid < 72) {
        const int idx = (bid - 8) * 256 + t;
        for (int i = idx; i < BATCH * HEADS * CPH * CPH; i += 64 * 256) g_S[i] = 0.f;
        for (int i = idx; i < BATCH * 2 * CH; i += 64 * 256) g_sumsq[i] = 0.f;
    } else {
        const int m = bid - 72;
        if (t < CH)
            Wb[(size_t)m * CH + t] = __float2half_rn(qkvw[(size_t)m * CH + t]);
    }
}

// ---------------- unified planar-B fp16 GEMM via mma.sync (R11 config) -----
#define VB_ROW 272
#define VB_BYTES (64 * VB_ROW)
#define SM_VB (3 * 16384)
#define SMEM_GEMM (1024 + SM_VB + 2 * VB_BYTES)

template <typename OT, bool SCALE, bool ABATCH>
__global__ void __launch_bounds__(256, 2)
gemm_planar(const __half* __restrict__ Ball, const __half* __restrict__ A,
            const float* __restrict__ bias, OT* __restrict__ Y, int Mtot,
            int chanPB, int chanOff,
            const float* __restrict__ mask, const float* __restrict__ tbp) {
    extern __shared__ __align__(16) char smraw[];
    uint32_t sbr = smem_u32(smraw);
    uint32_t sb = (sbr + 1023) & ~1023u;
    const int t = threadIdx.x;
    const int warp = t >> 5, lane = t & 31;
    const int wm = warp >> 2, wn = warp & 3;      // warp tile m64 x n32
    const int b = blockIdx.z;
    const int M0 = blockIdx.x * 128;
    const int N0 = blockIdx.y * 128;
    const __half* vbase = Ball + (size_t)(b * chanPB + chanOff) * HW;
    const __half* Ab = A + (ABATCH ? (size_t)b * 256 * CH : 0);

#pragma unroll
    for (int i = 0; i < 12; i++) {
        int u = t + i * 256;
        int ca = u >> 10, v = u & 1023;
        int row = v >> 3, q = v & 7;
        const void* src = Ab + (size_t)(M0 + row) * CH + ca * 64 + q * 8;
        cp16(sb + ca * 16384 + SWZ(row * 128 + q * 16), src,
             (M0 + row < Mtot) ? 16 : 0);
    }
#define VB_LOAD(ca) do {                                                           \
        uint32_t _dst = sb + SM_VB + (uint32_t)((ca) & 1) * VB_BYTES;              \
        _Pragma("unroll")                                                          \
        for (int _i = 0; _i < 4; _i++) {                                           \
            int _u = t + _i * 256;                                                 \
            int _kr = _u >> 4, _q = _u & 15;                                       \
            cp16(_dst + _kr * VB_ROW + _q * 16,                                    \
                 vbase + (size_t)((ca) * 64 + _kr) * HW + N0 + _q * 8, 16);        \
        }                                                                          \
        CP_COMMIT();                                                               \
    } while (0)

    VB_LOAD(0);
    VB_LOAD(1);

    float acc[4][4][4];
#pragma unroll
    for (int i = 0; i < 4; i++)
#pragma unroll
        for (int j = 0; j < 4; j++)
#pragma unroll
            for (int k = 0; k < 4; k++) acc[i][j][k] = 0.f;

    for (int bi = 0; bi < 3; bi++) {
        if (bi < 2) asm volatile("cp.async.wait_group 1;" ::: "memory");
        else        asm volatile("cp.async.wait_group 0;" ::: "memory");
        __syncthreads();

        const uint32_t abuf = sb + (uint32_t)bi * 16384;
        const uint32_t vbuf = sb + SM_VB + (uint32_t)(bi & 1) * VB_BYTES;
#pragma unroll
        for (int kk = 0; kk < 4; kk++) {
            uint32_t af[4][4];
#pragma unroll
            for (int mf = 0; mf < 4; mf++) {
                int row = wm * 64 + mf * 16 + (lane & 7) + ((lane & 8) ? 8 : 0);
                int cb = kk * 32 + ((lane & 16) ? 16 : 0);
                LDSM4(af[mf][0], af[mf][1], af[mf][2], af[mf][3],
                      abuf + SWZ(row * 128 + cb));
            }
#pragma unroll
            for (int nf2 = 0; nf2 < 2; nf2++) {
                int krow = kk * 16 + (lane & 7) + ((lane & 8) ? 8 : 0);
                int ncol = wn * 32 + nf2 * 16 + ((lane & 16) ? 8 : 0);
                uint32_t b0, b1, b2, b3;
                LDSM4T(b0, b1, b2, b3, vbuf + krow * VB_ROW + ncol * 2);
#pragma unroll
                for (int mf = 0; mf < 4; mf++) {
                    MMA16816(acc[mf][nf2 * 2 + 0], af[mf], b0, b1);
                    MMA16816(acc[mf][nf2 * 2 + 1], af[mf], b2, b3);
                }
            }
        }
        __syncthreads();
        if (bi + 2 < 3) VB_LOAD(bi + 2);
    }
#undef VB_LOAD

    const int g = lane >> 2, tg = lane & 3;
    const int nbase = N0 + wn * 32 + tg * 2;
    float2 sp[4];
    if (SCALE) {
        const float tb = fminf(fmaxf(*tbp, 0.1f), 0.5f);
        const float* mrow = mask + (size_t)b * HW;
#pragma unroll
        for (int nf = 0; nf < 4; nf++) {
            sp[nf].x = 1.f + tb * mrow[nbase + nf * 8];
            sp[nf].y = 1.f + tb * mrow[nbase + nf * 8 + 1];
        }
    }
#pragma unroll
    for (int mf = 0; mf < 4; mf++) {
#pragma unroll
        for (int half = 0; half < 2; half++) {
            int m = M0 + wm * 64 + mf * 16 + g + half * 8;
            if (m < Mtot) {
                float bs = bias[m];
                OT* yrow = Y + ((size_t)b * Mtot + m) * HW + nbase;
#pragma unroll
                for (int nf = 0; nf < 4; nf++) {
                    float v0 = acc[mf][nf][half * 2 + 0];
                    float v1 = acc[mf][nf][half * 2 + 1];
                    if (SCALE) { v0 = v0 * sp[nf].x; v1 = v1 * sp[nf].y; }
                    v0 += bs; v1 += bs;
                    if constexpr (sizeof(OT) == 4)
                        *(float2*)(yrow + nf * 8) = make_float2(v0, v1);
                    else
                        *(__half2*)(yrow + nf * 8) = __floats2half2_rn(v0, v1);
                }
            }
        }
    }
}

// ---------------- 3x3 depthwise conv (groups=576), 32-row tiles, fp16 in/out
__global__ void __launch_bounds__(256) dwconv_kernel(const __half* __restrict__ in,
                                                     const float* __restrict__ w,
                                                     const float* __restrict__ bias,
                                                     __half* __restrict__ out) {
    const int b = blockIdx.z, ch = blockIdx.y;
    const int t = threadIdx.x;
    const int r0 = blockIdx.x * 32;
    __shared__ __align__(16) float sm[34][132];
    const __half* src = in + ((size_t)b * QKVC + ch) * HW;

#pragma unroll
    for (int i = 0; i < 3; i++) {
        int idx = t + i * 256;
        if (idx < 544) {
            int rr = idx >> 4, c8 = (idx & 15) * 8;
            int gr = r0 - 1 + rr;
            float4 lo = make_float4(0, 0, 0, 0), hi = lo;
            if (gr >= 0 && gr < 128) {
                uint4 v = *(const uint4*)(src + gr * 128 + c8);
                h8_to_f2(v, &lo, &hi);
            }
            *(float4*)&sm[rr][c8] = lo;
            *(float4*)&sm[rr][c8 + 4] = hi;
        }
    }
    float wv[9];
#pragma unroll
    for (int i = 0; i < 9; i++) wv[i] = w[ch * 9 + i];
    const float bsv = bias[ch];
    __syncthreads();

    const int lr = (t >> 4) * 2;
    const int xo = (t & 15) * 8;
    float R[4][16];
#pragma unroll
    for (int dy = 0; dy < 4; dy++) {
        const float* row = sm[lr + dy];
        float4 v;
        v = (xo > 0) ? *(const float4*)(row + xo - 4) : make_float4(0, 0, 0, 0);
        R[dy][0] = v.x; R[dy][1] = v.y; R[dy][2] = v.z; R[dy][3] = v.w;
        v = *(const float4*)(row + xo);
        R[dy][4] = v.x; R[dy][5] = v.y; R[dy][6] = v.z; R[dy][7] = v.w;
        v = *(const float4*)(row + xo + 4);
        R[dy][8] = v.x; R[dy][9] = v.y; R[dy][10] = v.z; R[dy][11] = v.w;
        v = (xo < 120) ? *(const float4*)(row + xo + 8) : make_float4(0, 0, 0, 0);
        R[dy][12] = v.x; R[dy][13] = v.y; R[dy][14] = v.z; R[dy][15] = v.w;
    }
    float ss = 0.f;
#pragma unroll
    for (int rr2 = 0; rr2 < 2; rr2++) {
        float o[8];
#pragma unroll
        for (int i = 0; i < 8; i++) {
            float a = bsv;
#pragma unroll
            for (int dy = 0; dy < 3; dy++)
                a += wv[dy * 3 + 0] * R[rr2 + dy][3 + i] +
                     wv[dy * 3 + 1] * R[rr2 + dy][4 + i] +
                     wv[dy * 3 + 2] * R[rr2 + dy][5 + i];
            o[i] = a; ss += a * a;
        }
        __align__(16) __half oh[8];
#pragma unroll
        for (int i = 0; i < 8; i++) oh[i] = __float2half_rn(o[i]);
        *(uint4*)(out + ((size_t)b * QKVC + ch) * HW + (r0 + lr + rr2) * 128 + xo) =
            *(const uint4*)oh;
    }

    if (ch < 2 * CH) {
#pragma unroll
        for (int off = 16; off > 0; off >>= 1)
            ss += __shfl_xor_sync(0xFFFFFFFFu, ss, off);
        if ((t & 31) == 0) atomicAdd(&g_sumsq[b * 2 * CH + ch], ss);
    }
}

// ---------------- attention scores via mma.sync: S[bh] += q·k^T (16-way split)
// pad rows 48..63 zeroed ONCE; loader issues only the 48 real rows per matrix
#define ATM_SMEM (1024 + 2 * 16384)

__global__ void __launch_bounds__(256) attn_mma(const __half* __restrict__ qkv) {
    extern __shared__ __align__(16) char atraw[];
    uint32_t sbr = smem_u32(atraw);
    uint32_t sb = (sbr + 1023) & ~1023u;
    char* smc = atraw + (sb - sbr);
    const int bh = blockIdx.y, b = bh >> 2, h = bh & 3;
    const int t = threadIdx.x;
    const int warp = t >> 5, lane = t & 31;
    const int wm = warp >> 2, wn = warp & 3;      // warp tile m32 x n16
    const __half* qbase = qkv + ((size_t)b * QKVC + h * CPH) * HW;
    const __half* kbase = qbase + (size_t)CH * HW;
    const int n0 = blockIdx.x * 1024;             // 16 iterations of k64

    // zero pad rows 48..63 of q and k regions in BOTH buffers (one time).
    // SWZ only permutes bits [4:6] (within a 128B row), so linear zeroing of
    // the byte range [48*128, 64*128) covers the swizzled layout exactly.
    {
        // 4 regions x 2048 bytes = 8192 bytes = 512 uint4 -> 2 per thread
#pragma unroll
        for (int i = 0; i < 2; i++) {
            int u = t + i * 256;                  // 0..511
            int reg = u >> 7, off = (u & 127) * 16;
            uint32_t base = (uint32_t)(reg & 1) * 8192 + (uint32_t)(reg >> 1) * 16384;
            *(uint4*)(smc + base + 6144 + off) = make_uint4(0, 0, 0, 0);
        }
    }

    // loader: 768 real cp16 slots (q rows 0..47, k rows 0..47)
#define ATM_LOAD(it) do {                                                          \
        const int _nw = n0 + (it) * 64;                                            \
        _Pragma("unroll")                                                          \
        for (int _i = 0; _i < 3; _i++) {                                           \
            int _u = t + _i * 256;                                                 \
            int _isK = _u >= 384;                                                  \
            int _v = _isK ? (_u - 384) : _u;                                       \
            int _row = _v >> 3, _q8 = _v & 7;                                      \
            const __half* _src = (_isK ? kbase : qbase) + (size_t)_row * HW + _nw + _q8 * 8; \
            cp16(sb + (uint32_t)((it) & 1) * 16384 + (_isK ? 8192 : 0) +           \
                     SWZ(_row * 128 + _q8 * 16),                                   \
                 _src, 16);                                                        \
        }                                                                          \
        CP_COMMIT();                                                               \
    } while (0)

    ATM_LOAD(0);
    ATM_LOAD(1);

    float acc[2][2][4];
#pragma unroll
    for (int i = 0; i < 2; i++)
#pragma unroll
        for (int j = 0; j < 2; j++)
#pragma unroll
            for (int k = 0; k < 4; k++) acc[i][j][k] = 0.f;

    for (int bi = 0; bi < 16; bi++) {
        if (bi < 15) asm volatile("cp.async.wait_group 1;" ::: "memory");
        else         asm volatile("cp.async.wait_group 0;" ::: "memory");
        __syncthreads();
        const uint32_t qbuf = sb + (uint32_t)(bi & 1) * 16384;
        const uint32_t kbuf = qbuf + 8192;
#pragma unroll
        for (int kk = 0; kk < 4; kk++) {
            uint32_t af[2][4];
#pragma unroll
            for (int mf = 0; mf < 2; mf++) {
                int row = wm * 32 + mf * 16 + (lane & 7) + ((lane & 8) ? 8 : 0);
                int cb = kk * 32 + ((lane & 16) ? 16 : 0);
                LDSM4(af[mf][0], af[mf][1], af[mf][2], af[mf][3],
                      qbuf + SWZ(row * 128 + cb));
            }
            int rowb = wn * 16 + (lane & 7) + ((lane & 16) ? 8 : 0);
            int cbb = kk * 32 + ((lane & 8) ? 16 : 0);
            uint32_t b0, b1, b2, b3;
            LDSM4(b0, b1, b2, b3, kbuf + SWZ(rowb * 128 + cbb));
#pragma unroll
            for (int mf = 0; mf < 2; mf++) {
                MMA16816(acc[mf][0], af[mf], b0, b1);
                MMA16816(acc[mf][1], af[mf], b2, b3);
            }
        }
        __syncthreads();
        if (bi + 2 < 16) ATM_LOAD(bi + 2);
    }
#undef ATM_LOAD

    float* Sb = g_S + (size_t)bh * CPH * CPH;
    const int g = lane >> 2, tg = lane & 3;
#pragma unroll
    for (int mf = 0; mf < 2; mf++)
#pragma unroll
        for (int half = 0; half < 2; half++) {
            int m = wm * 32 + mf * 16 + g + half * 8;
            if (m < CPH) {
#pragma unroll
                for (int nf = 0; nf < 2; nf++)
#pragma unroll
                    for (int j = 0; j < 2; j++) {
                        int d = wn * 16 + nf * 8 + tg * 2 + j;
                        if (d < CPH)
                            atomicAdd(&Sb[m * CPH + d], acc[mf][nf][half * 2 + j]);
                    }
            }
        }
}

// ---------------- fused softmax (norm+temp) + Weff = W2 · blockdiag(A) -----
__global__ void __launch_bounds__(192) softmax_weff(const float* __restrict__ det,
                                                    const float* __restrict__ smo,
                                                    const float* __restrict__ W2,
                                                    __half* __restrict__ Weff) {
    const int b = blockIdx.x, t = threadIdx.x;   // 192 threads
    __shared__ float As[HEADS * CPH * CPH];

    {
        const int h = t / CPH, r = t % CPH;
        const float tl = g_masksum[b] / (float)HW;
        const float temp = det[h] * tl + smo[h] * (1.f - tl);
        const float invq = 1.f / fmaxf(sqrtf(g_sumsq[b * 2 * CH + h * CPH + r]), 1e-12f);
        const float* Srow = g_S + ((size_t)(b * HEADS + h) * CPH + r) * CPH;
        float vals[CPH];
        float mx = -1e30f;
#pragma unroll
        for (int d = 0; d < CPH; d++) {
            float invk = 1.f / fmaxf(sqrtf(g_sumsq[b * 2 * CH + CH + h * CPH + d]), 1e-12f);
            float v = Srow[d] * invq * invk * temp;
            vals[d] = v;
            mx = fmaxf(mx, v);
        }
        float sum = 0.f;
#pragma unroll
        for (int d = 0; d < CPH; d++) { vals[d] = expf(vals[d] - mx); sum += vals[d]; }
        float inv = 1.f / sum;
        float* Arow = As + (h * CPH + r) * CPH;
#pragma unroll
        for (int d = 0; d < CPH; d++) Arow[d] = vals[d] * inv;
    }
    __syncthreads();

    const int m = t;
    __half* wrow_out = Weff + ((size_t)b * 256 + m) * CH;
#pragma unroll
    for (int h = 0; h < HEADS; h++) {
        float wr[CPH];
#pragma unroll
        for (int cc = 0; cc < CPH; cc++) wr[cc] = W2[(size_t)m * CH + h * CPH + cc];
        const float* Ah = As + h * CPH * CPH;
        for (int d0 = 0; d0 < CPH; d0 += 4) {
            float s0 = 0.f, s1 = 0.f, s2 = 0.f, s3 = 0.f;
#pragma unroll
            for (int cc = 0; cc < CPH; cc++) {
                float w = wr[cc];
                const float* ar = Ah + cc * CPH + d0;
                s0 += w * ar[0]; s1 += w * ar[1];
                s2 += w * ar[2]; s3 += w * ar[3];
            }
            wrow_out[h * CPH + d0 + 0] = __float2half_rn(s0);
            wrow_out[h * CPH + d0 + 1] = __float2half_rn(s1);
            wrow_out[h * CPH + d0 + 2] = __float2half_rn(s2);
            wrow_out[h * CPH + d0 + 3] = __float2half_rn(s3);
        }
    }
}

// ---------------- host launcher ----------------
extern "C" void kernel_launch(void* const* d_in, const int* in_sizes, int n_in,
                              void* d_out, int out_size) {
    const float* x    = (const float*)d_in[0];
    const float* mask = (const float*)d_in[1];
    const float* qkvw = (const float*)d_in[2];
    const float* qkvb = (const float*)d_in[3];
    const float* dww  = (const float*)d_in[4];
    const float* dwb  = (const float*)d_in[5];
    const float* outw = (const float*)d_in[6];
    const float* outb = (const float*)d_in[7];
    const float* det  = (const float*)d_in[8];
    const float* smo  = (const float*)d_in[9];
    const float* tbp  = (const float*)d_in[10];
    float* y = (float*)d_out;

    void *p_q0 = nullptr, *p_q1 = nullptr, *p_xh = nullptr, *p_wb = nullptr, *p_we = nullptr;
    cudaGetSymbolAddress(&p_q0, g_q0h);
    cudaGetSymbolAddress(&p_q1, g_q1h);
    cudaGetSymbolAddress(&p_xh, g_xh4);
    cudaGetSymbolAddress(&p_wb, g_wb4);
    cudaGetSymbolAddress(&p_we, g_weff);

    auto gemm_qkv = gemm_planar<__half, false, false>;
    auto gemm_out = gemm_planar<float, true, true>;
    cudaFuncSetAttribute(gemm_qkv, cudaFuncAttributeMaxDynamicSharedMemorySize, SMEM_GEMM);
    cudaFuncSetAttribute(gemm_out, cudaFuncAttributeMaxDynamicSharedMemorySize, SMEM_GEMM);
    cudaFuncSetAttribute(attn_mma, cudaFuncAttributeMaxDynamicSharedMemorySize, ATM_SMEM);

    // setup: mask sums + zeroing + weight convert + x fp32->fp16 (one launch)
    setup_kernel<<<648 + 6144, 256>>>(mask, qkvw, (__half*)p_wb, x, (__half*)p_xh);
    // qkv 1x1 conv: planar-B fp16 GEMM -> fp16 planar output
    gemm_qkv<<<dim3(5, HW / 128, BATCH), 256, SMEM_GEMM>>>(
        (const __half*)p_xh, (const __half*)p_wb, qkvb, (__half*)p_q0, QKVC,
        CH, 0, nullptr, nullptr);
    // 3x3 depthwise (+ fused q/k sum-of-squares)
    dwconv_kernel<<<dim3(4, QKVC, BATCH), 256>>>(
        (const __half*)p_q0, dww, dwb, (__half*)p_q1);
    // channel attention scores via tensor cores (16-way split-K)
    attn_mma<<<dim3(16, BATCH * HEADS), 256, ATM_SMEM>>>((const __half*)p_q1);
    // softmax + Weff fold (one launch)
    softmax_weff<<<BATCH, 192>>>(det, smo, outw, (__half*)p_we);
    // y = (Weff @ v) * s(n) + outb
    gemm_out<<<dim3(2, HW / 128, BATCH), 256, SMEM_GEMM>>>(
        (const __half*)p_q1, (const __half*)p_we, outb, y, CH,
        QKVC, 2 * CH, mask, tbp);
}

// round 16
// speedup vs baseline: 1.0759x; 1.0137x over previous
#include <cuda_runtime.h>
#include <cuda_fp16.h>
#include <math.h>
#include <stdint.h>

// Problem constants
#define BATCH 8
#define CH    192
#define QKVC  576
#define HW    16384
#define HEADS 4
#define CPH   48

// ---------------- scratch (static device memory; no allocs) ----------------
__device__ uint4 g_q0h[(size_t)BATCH * QKVC * HW * 2 / 16];   // fp16 qkv after 1x1 (planar)
__device__ uint4 g_q1h[(size_t)BATCH * QKVC * HW * 2 / 16];   // fp16 qkv after dw (planar)
__device__ float g_sumsq[BATCH * 2 * CH];
__device__ float g_S[BATCH * HEADS * CPH * CPH];
__device__ float g_masksum[BATCH];
__device__ uint4 g_xh4[(size_t)BATCH * CH * HW * 2 / 16];     // [B][192][HW] fp16 planar
__device__ uint4 g_wb4[(size_t)(QKVC + 64) * CH * 2 / 16];    // [576(+pad)][192] fp16
__device__ uint4 g_weff[(size_t)BATCH * 256 * CH * 2 / 16];   // [B][192(+pad)][192] fp16

// ---------------- helpers ----------------
__device__ __forceinline__ uint32_t smem_u32(const void* p) {
    uint32_t a;
    asm("{ .reg .u64 t; cvta.to.shared.u64 t, %1; cvt.u32.u64 %0, t; }" : "=r"(a) : "l"(p));
    return a;
}
#define SWZ(off) ((off) ^ (((off) >> 3) & 0x70))

__device__ __forceinline__ void cp16(uint32_t dst, const void* src, int srcsz) {
    asm volatile("cp.async.cg.shared.global [%0], [%1], 16, %2;"
                 :: "r"(dst), "l"(src), "r"(srcsz) : "memory");
}
#define CP_COMMIT() asm volatile("cp.async.commit_group;" ::: "memory")

#define LDSM4(r0, r1, r2, r3, addr)                                            \
    asm volatile("ldmatrix.sync.aligned.m8n8.x4.shared.b16 {%0,%1,%2,%3}, [%4];" \
                 : "=r"(r0), "=r"(r1), "=r"(r2), "=r"(r3) : "r"(addr))

#define LDSM4T(r0, r1, r2, r3, addr)                                           \
    asm volatile("ldmatrix.sync.aligned.m8n8.x4.trans.shared.b16 {%0,%1,%2,%3}, [%4];" \
                 : "=r"(r0), "=r"(r1), "=r"(r2), "=r"(r3) : "r"(addr))

#define MMA16816(c, a, b0, b1)                                                 \
    asm volatile("mma.sync.aligned.m16n8k16.row.col.f32.f16.f16.f32 "          \
                 "{%0,%1,%2,%3},{%4,%5,%6,%7},{%8,%9},{%0,%1,%2,%3};"          \
                 : "+f"((c)[0]), "+f"((c)[1]), "+f"((c)[2]), "+f"((c)[3])      \
                 : "r"((a)[0]), "r"((a)[1]), "r"((a)[2]), "r"((a)[3]),         \
                   "r"(b0), "r"(b1))

__device__ __forceinline__ void h8_to_f2(const uint4 v, float4* lo, float4* hi) {
    const __half2* h2 = (const __half2*)&v;
    float2 a = __half22float2(h2[0]);
    float2 b = __half22float2(h2[1]);
    float2 c = __half22float2(h2[2]);
    float2 d = __half22float2(h2[3]);
    *lo = make_float4(a.x, a.y, b.x, b.y);
    *hi = make_float4(c.x, c.y, d.x, d.y);
}

// ---------------- setup: mask sums, zeroing, weight convert, x fp32->fp16 --
__global__ void __launch_bounds__(256) setup_kernel(const float* __restrict__ mask,
                                                    const float* __restrict__ qkvw,
                                                    __half* __restrict__ Wb,
                                                    const float* __restrict__ X,
                                                    __half* __restrict__ Xh) {
    const int bid = blockIdx.x, t = threadIdx.x;
    if (bid >= 648) {
        const size_t total4 = (size_t)BATCH * CH * HW / 4;
        for (size_t i = (size_t)(bid - 648) * 256 + t; i < total4; i += (size_t)6144 * 256) {
            float4 v = ((const float4*)X)[i];
            __half2 lo = __floats2half2_rn(v.x, v.y);
            __half2 hi = __floats2half2_rn(v.z, v.w);
            uint2 o;
            o.x = *(uint32_t*)&lo;
            o.y = *(uint32_t*)&hi;
            ((uint2*)Xh)[i] = o;
        }
    } else if (bid < 8) {
        const int b = bid;
        const float4* m4 = (const float4*)(mask + (size_t)b * HW);
        float s = 0.f;
        for (int i = t; i < HW / 4; i += 256) {
            float4 v = m4[i];
            s += v.x + v.y + v.z + v.w;
        }
#pragma unroll
        for (int o = 16; o > 0; o >>= 1) s += __shfl_xor_sync(0xFFFFFFFFu, s, o);
        __shared__ float red[8];
        if ((t & 31) == 0) red[t >> 5] = s;
        __syncthreads();
        if (t == 0) {
            float tot = 0.f;
#pragma unroll
            for (int i = 0; i < 8; i++) tot += red[i];
            g_masksum[b] = tot;
        }
    } else if (bid < 72) {
        const int idx = (bid - 8) * 256 + t;
        for (int i = idx; i < BATCH * HEADS * CPH * CPH; i += 64 * 256) g_S[i] = 0.f;
        for (int i = idx; i < BATCH * 2 * CH; i += 64 * 256) g_sumsq[i] = 0.f;
    } else {
        const int m = bid - 72;
        if (t < CH)
            Wb[(size_t)m * CH + t] = __float2half_rn(qkvw[(size_t)m * CH + t]);
    }
}

// ---------------- unified planar-B fp16 GEMM via mma.sync, M-tile 96 -------
// A chunk = [96 m][64 k] = 12288B; 3 chunks resident (36KB). Warp tile m48xn32.
#define AC_BYTES 12288
#define SM_VB (3 * AC_BYTES)
#define VB_ROW 272
#define VB_BYTES (64 * VB_ROW)
#define SMEM_GEMM (1024 + SM_VB + 2 * VB_BYTES)

template <typename OT, bool SCALE, bool ABATCH>
__global__ void __launch_bounds__(256, 2)
gemm_planar(const __half* __restrict__ Ball, const __half* __restrict__ A,
            const float* __restrict__ bias, OT* __restrict__ Y, int Mtot,
            int chanPB, int chanOff,
            const float* __restrict__ mask, const float* __restrict__ tbp) {
    extern __shared__ __align__(16) char smraw[];
    uint32_t sbr = smem_u32(smraw);
    uint32_t sb = (sbr + 1023) & ~1023u;
    const int t = threadIdx.x;
    const int warp = t >> 5, lane = t & 31;
    const int wm = warp >> 2, wn = warp & 3;      // warp tile m48 x n32
    const int b = blockIdx.z;
    const int M0 = blockIdx.x * 96;
    const int N0 = blockIdx.y * 128;
    const __half* vbase = Ball + (size_t)(b * chanPB + chanOff) * HW;
    const __half* Ab = A + (ABATCH ? (size_t)b * 256 * CH : 0);

    // A: 3 chunks of [96 m][64 k] -> 2304 16B units, 9 per thread
#pragma unroll
    for (int i = 0; i < 9; i++) {
        int u = t + i * 256;
        int ca = u / 768, v = u - ca * 768;
        int row = v >> 3, q = v & 7;
        const void* src = Ab + (size_t)(M0 + row) * CH + ca * 64 + q * 8;
        cp16(sb + ca * AC_BYTES + SWZ(row * 128 + q * 16), src,
             (M0 + row < Mtot) ? 16 : 0);
    }
#define VB_LOAD(ca) do {                                                           \
        uint32_t _dst = sb + SM_VB + (uint32_t)((ca) & 1) * VB_BYTES;              \
        _Pragma("unroll")                                                          \
        for (int _i = 0; _i < 4; _i++) {                                           \
            int _u = t + _i * 256;                                                 \
            int _kr = _u >> 4, _q = _u & 15;                                       \
            cp16(_dst + _kr * VB_ROW + _q * 16,                                    \
                 vbase + (size_t)((ca) * 64 + _kr) * HW + N0 + _q * 8, 16);        \
        }                                                                          \
        CP_COMMIT();                                                               \
    } while (0)

    VB_LOAD(0);
    VB_LOAD(1);

    float acc[3][4][4];
#pragma unroll
    for (int i = 0; i < 3; i++)
#pragma unroll
        for (int j = 0; j < 4; j++)
#pragma unroll
            for (int k = 0; k < 4; k++) acc[i][j][k] = 0.f;

    for (int bi = 0; bi < 3; bi++) {
        if (bi < 2) asm volatile("cp.async.wait_group 1;" ::: "memory");
        else        asm volatile("cp.async.wait_group 0;" ::: "memory");
        __syncthreads();

        const uint32_t abuf = sb + (uint32_t)bi * AC_BYTES;
        const uint32_t vbuf = sb + SM_VB + (uint32_t)(bi & 1) * VB_BYTES;
#pragma unroll
        for (int kk = 0; kk < 4; kk++) {
            uint32_t af[3][4];
#pragma unroll
            for (int mf = 0; mf < 3; mf++) {
                int row = wm * 48 + mf * 16 + (lane & 7) + ((lane & 8) ? 8 : 0);
                int cb = kk * 32 + ((lane & 16) ? 16 : 0);
                LDSM4(af[mf][0], af[mf][1], af[mf][2], af[mf][3],
                      abuf + SWZ(row * 128 + cb));
            }
#pragma unroll
            for (int nf2 = 0; nf2 < 2; nf2++) {
                int krow = kk * 16 + (lane & 7) + ((lane & 8) ? 8 : 0);
                int ncol = wn * 32 + nf2 * 16 + ((lane & 16) ? 8 : 0);
                uint32_t b0, b1, b2, b3;
                LDSM4T(b0, b1, b2, b3, vbuf + krow * VB_ROW + ncol * 2);
#pragma unroll
                for (int mf = 0; mf < 3; mf++) {
                    MMA16816(acc[mf][nf2 * 2 + 0], af[mf], b0, b1);
                    MMA16816(acc[mf][nf2 * 2 + 1], af[mf], b2, b3);
                }
            }
        }
        __syncthreads();
        if (bi + 2 < 3) VB_LOAD(bi + 2);
    }
#undef VB_LOAD

    const int g = lane >> 2, tg = lane & 3;
    const int nbase = N0 + wn * 32 + tg * 2;
    float2 sp[4];
    if (SCALE) {
        const float tb = fminf(fmaxf(*tbp, 0.1f), 0.5f);
        const float* mrow = mask + (size_t)b * HW;
#pragma unroll
        for (int nf = 0; nf < 4; nf++) {
            sp[nf].x = 1.f + tb * mrow[nbase + nf * 8];
            sp[nf].y = 1.f + tb * mrow[nbase + nf * 8 + 1];
        }
    }
#pragma unroll
    for (int mf = 0; mf < 3; mf++) {
#pragma unroll
        for (int half = 0; half < 2; half++) {
            int m = M0 + wm * 48 + mf * 16 + g + half * 8;
            if (m < Mtot) {
                float bs = bias[m];
                OT* yrow = Y + ((size_t)b * Mtot + m) * HW + nbase;
#pragma unroll
                for (int nf = 0; nf < 4; nf++) {
                    float v0 = acc[mf][nf][half * 2 + 0];
                    float v1 = acc[mf][nf][half * 2 + 1];
                    if (SCALE) { v0 = v0 * sp[nf].x; v1 = v1 * sp[nf].y; }
                    v0 += bs; v1 += bs;
                    if constexpr (sizeof(OT) == 4)
                        *(float2*)(yrow + nf * 8) = make_float2(v0, v1);
                    else
                        *(__half2*)(yrow + nf * 8) = __floats2half2_rn(v0, v1);
                }
            }
        }
    }
}

// ---------------- 3x3 depthwise conv (groups=576), 32-row tiles, fp16 in/out
__global__ void __launch_bounds__(256) dwconv_kernel(const __half* __restrict__ in,
                                                     const float* __restrict__ w,
                                                     const float* __restrict__ bias,
                                                     __half* __restrict__ out) {
    const int b = blockIdx.z, ch = blockIdx.y;
    const int t = threadIdx.x;
    const int r0 = blockIdx.x * 32;
    __shared__ __align__(16) float sm[34][132];
    const __half* src = in + ((size_t)b * QKVC + ch) * HW;

#pragma unroll
    for (int i = 0; i < 3; i++) {
        int idx = t + i * 256;
        if (idx < 544) {
            int rr = idx >> 4, c8 = (idx & 15) * 8;
            int gr = r0 - 1 + rr;
            float4 lo = make_float4(0, 0, 0, 0), hi = lo;
            if (gr >= 0 && gr < 128) {
                uint4 v = *(const uint4*)(src + gr * 128 + c8);
                h8_to_f2(v, &lo, &hi);
            }
            *(float4*)&sm[rr][c8] = lo;
            *(float4*)&sm[rr][c8 + 4] = hi;
        }
    }
    float wv[9];
#pragma unroll
    for (int i = 0; i < 9; i++) wv[i] = w[ch * 9 + i];
    const float bsv = bias[ch];
    __syncthreads();

    const int lr = (t >> 4) * 2;
    const int xo = (t & 15) * 8;
    float R[4][16];
#pragma unroll
    for (int dy = 0; dy < 4; dy++) {
        const float* row = sm[lr + dy];
        float4 v;
        v = (xo > 0) ? *(const float4*)(row + xo - 4) : make_float4(0, 0, 0, 0);
        R[dy][0] = v.x; R[dy][1] = v.y; R[dy][2] = v.z; R[dy][3] = v.w;
        v = *(const float4*)(row + xo);
        R[dy][4] = v.x; R[dy][5] = v.y; R[dy][6] = v.z; R[dy][7] = v.w;
        v = *(const float4*)(row + xo + 4);
        R[dy][8] = v.x; R[dy][9] = v.y; R[dy][10] = v.z; R[dy][11] = v.w;
        v = (xo < 120) ? *(const float4*)(row + xo + 8) : make_float4(0, 0, 0, 0);
        R[dy][12] = v.x; R[dy][13] = v.y; R[dy][14] = v.z; R[dy][15] = v.w;
    }
    float ss = 0.f;
#pragma unroll
    for (int rr2 = 0; rr2 < 2; rr2++) {
        float o[8];
#pragma unroll
        for (int i = 0; i < 8; i++) {
            float a = bsv;
#pragma unroll
            for (int dy = 0; dy < 3; dy++)
                a += wv[dy * 3 + 0] * R[rr2 + dy][3 + i] +
                     wv[dy * 3 + 1] * R[rr2 + dy][4 + i] +
                     wv[dy * 3 + 2] * R[rr2 + dy][5 + i];
            o[i] = a; ss += a * a;
        }
        __align__(16) __half oh[8];
#pragma unroll
        for (int i = 0; i < 8; i++) oh[i] = __float2half_rn(o[i]);
        *(uint4*)(out + ((size_t)b * QKVC + ch) * HW + (r0 + lr + rr2) * 128 + xo) =
            *(const uint4*)oh;
    }

    if (ch < 2 * CH) {
#pragma unroll
        for (int off = 16; off > 0; off >>= 1)
            ss += __shfl_xor_sync(0xFFFFFFFFu, ss, off);
        if ((t & 31) == 0) atomicAdd(&g_sumsq[b * 2 * CH + ch], ss);
    }
}

// ---------------- attention scores via mma.sync: S[bh] += q·k^T (16-way split)
#define ATM_SMEM (1024 + 2 * 16384)

__global__ void __launch_bounds__(256) attn_mma(const __half* __restrict__ qkv) {
    extern __shared__ __align__(16) char atraw[];
    uint32_t sbr = smem_u32(atraw);
    uint32_t sb = (sbr + 1023) & ~1023u;
    char* smc = atraw + (sb - sbr);
    const int bh = blockIdx.y, b = bh >> 2, h = bh & 3;
    const int t = threadIdx.x;
    const int warp = t >> 5, lane = t & 31;
    const int wm = warp >> 2, wn = warp & 3;      // warp tile m32 x n16
    const __half* qbase = qkv + ((size_t)b * QKVC + h * CPH) * HW;
    const __half* kbase = qbase + (size_t)CH * HW;
    const int n0 = blockIdx.x * 1024;             // 16 iterations of k64

    // zero pad rows 48..63 of q and k regions in BOTH buffers (once)
    {
#pragma unroll
        for (int i = 0; i < 2; i++) {
            int u = t + i * 256;
            int reg = u >> 7, off = (u & 127) * 16;
            uint32_t base = (uint32_t)(reg & 1) * 8192 + (uint32_t)(reg >> 1) * 16384;
            *(uint4*)(smc + base + 6144 + off) = make_uint4(0, 0, 0, 0);
        }
    }

#define ATM_LOAD(it) do {                                                          \
        const int _nw = n0 + (it) * 64;                                            \
        _Pragma("unroll")                                                          \
        for (int _i = 0; _i < 3; _i++) {                                           \
            int _u = t + _i * 256;                                                 \
            int _isK = _u >= 384;                                                  \
            int _v = _isK ? (_u - 384) : _u;                                       \
            int _row = _v >> 3, _q8 = _v & 7;                                      \
            const __half* _src = (_isK ? kbase : qbase) + (size_t)_row * HW + _nw + _q8 * 8; \
            cp16(sb + (uint32_t)((it) & 1) * 16384 + (_isK ? 8192 : 0) +           \
                     SWZ(_row * 128 + _q8 * 16),                                   \
                 _src, 16);                                                        \
        }                                                                          \
        CP_COMMIT();                                                               \
    } while (0)

    ATM_LOAD(0);
    ATM_LOAD(1);

    float acc[2][2][4];
#pragma unroll
    for (int i = 0; i < 2; i++)
#pragma unroll
        for (int j = 0; j < 2; j++)
#pragma unroll
            for (int k = 0; k < 4; k++) acc[i][j][k] = 0.f;

    for (int bi = 0; bi < 16; bi++) {
        if (bi < 15) asm volatile("cp.async.wait_group 1;" ::: "memory");
        else         asm volatile("cp.async.wait_group 0;" ::: "memory");
        __syncthreads();
        const uint32_t qbuf = sb + (uint32_t)(bi & 1) * 16384;
        const uint32_t kbuf = qbuf + 8192;
#pragma unroll
        for (int kk = 0; kk < 4; kk++) {
            uint32_t af[2][4];
#pragma unroll
            for (int mf = 0; mf < 2; mf++) {
                int row = wm * 32 + mf * 16 + (lane & 7) + ((lane & 8) ? 8 : 0);
                int cb = kk * 32 + ((lane & 16) ? 16 : 0);
                LDSM4(af[mf][0], af[mf][1], af[mf][2], af[mf][3],
                      qbuf + SWZ(row * 128 + cb));
            }
            int rowb = wn * 16 + (lane & 7) + ((lane & 16) ? 8 : 0);
            int cbb = kk * 32 + ((lane & 8) ? 16 : 0);
            uint32_t b0, b1, b2, b3;
            LDSM4(b0, b1, b2, b3, kbuf + SWZ(rowb * 128 + cbb));
#pragma unroll
            for (int mf = 0; mf < 2; mf++) {
                MMA16816(acc[mf][0], af[mf], b0, b1);
                MMA16816(acc[mf][1], af[mf], b2, b3);
            }
        }
        __syncthreads();
        if (bi + 2 < 16) ATM_LOAD(bi + 2);
    }
#undef ATM_LOAD

    float* Sb = g_S + (size_t)bh * CPH * CPH;
    const int g = lane >> 2, tg = lane & 3;
#pragma unroll
    for (int mf = 0; mf < 2; mf++)
#pragma unroll
        for (int half = 0; half < 2; half++) {
            int m = wm * 32 + mf * 16 + g + half * 8;
            if (m < CPH) {
#pragma unroll
                for (int nf = 0; nf < 2; nf++)
#pragma unroll
                    for (int j = 0; j < 2; j++) {
                        int d = wn * 16 + nf * 8 + tg * 2 + j;
                        if (d < CPH)
                            atomicAdd(&Sb[m * CPH + d], acc[mf][nf][half * 2 + j]);
                    }
            }
        }
}

// ---------------- fused softmax (norm+temp) + Weff = W2 · blockdiag(A) -----
__global__ void __launch_bounds__(192) softmax_weff(const float* __restrict__ det,
                                                    const float* __restrict__ smo,
                                                    const float* __restrict__ W2,
                                                    __half* __restrict__ Weff) {
    const int b = blockIdx.x, t = threadIdx.x;   // 192 threads
    __shared__ float As[HEADS * CPH * CPH];

    {
        const int h = t / CPH, r = t % CPH;
        const float tl = g_masksum[b] / (float)HW;
        const float temp = det[h] * tl + smo[h] * (1.f - tl);
        const float invq = 1.f / fmaxf(sqrtf(g_sumsq[b * 2 * CH + h * CPH + r]), 1e-12f);
        const float* Srow = g_S + ((size_t)(b * HEADS + h) * CPH + r) * CPH;
        float vals[CPH];
        float mx = -1e30f;
#pragma unroll
        for (int d = 0; d < CPH; d++) {
            float invk = 1.f / fmaxf(sqrtf(g_sumsq[b * 2 * CH + CH + h * CPH + d]), 1e-12f);
            float v = Srow[d] * invq * invk * temp;
            vals[d] = v;
            mx = fmaxf(mx, v);
        }
        float sum = 0.f;
#pragma unroll
        for (int d = 0; d < CPH; d++) { vals[d] = expf(vals[d] - mx); sum += vals[d]; }
        float inv = 1.f / sum;
        float* Arow = As + (h * CPH + r) * CPH;
#pragma unroll
        for (int d = 0; d < CPH; d++) Arow[d] = vals[d] * inv;
    }
    __syncthreads();

    const int m = t;
    __half* wrow_out = Weff + ((size_t)b * 256 + m) * CH;
#pragma unroll
    for (int h = 0; h < HEADS; h++) {
        float wr[CPH];
#pragma unroll
        for (int cc = 0; cc < CPH; cc++) wr[cc] = W2[(size_t)m * CH + h * CPH + cc];
        const float* Ah = As + h * CPH * CPH;
        for (int d0 = 0; d0 < CPH; d0 += 4) {
            float s0 = 0.f, s1 = 0.f, s2 = 0.f, s3 = 0.f;
#pragma unroll
            for (int cc = 0; cc < CPH; cc++) {
                float w = wr[cc];
                const float* ar = Ah + cc * CPH + d0;
                s0 += w * ar[0]; s1 += w * ar[1];
                s2 += w * ar[2]; s3 += w * ar[3];
            }
            wrow_out[h * CPH + d0 + 0] = __float2half_rn(s0);
            wrow_out[h * CPH + d0 + 1] = __float2half_rn(s1);
            wrow_out[h * CPH + d0 + 2] = __float2half_rn(s2);
            wrow_out[h * CPH + d0 + 3] = __float2half_rn(s3);
        }
    }
}

// ---------------- host launcher ----------------
extern "C" void kernel_launch(void* const* d_in, const int* in_sizes, int n_in,
                              void* d_out, int out_size) {
    const float* x    = (const float*)d_in[0];
    const float* mask = (const float*)d_in[1];
    const float* qkvw = (const float*)d_in[2];
    const float* qkvb = (const float*)d_in[3];
    const float* dww  = (const float*)d_in[4];
    const float* dwb  = (const float*)d_in[5];
    const float* outw = (const float*)d_in[6];
    const float* outb = (const float*)d_in[7];
    const float* det  = (const float*)d_in[8];
    const float* smo  = (const float*)d_in[9];
    const float* tbp  = (const float*)d_in[10];
    float* y = (float*)d_out;

    void *p_q0 = nullptr, *p_q1 = nullptr, *p_xh = nullptr, *p_wb = nullptr, *p_we = nullptr;
    cudaGetSymbolAddress(&p_q0, g_q0h);
    cudaGetSymbolAddress(&p_q1, g_q1h);
    cudaGetSymbolAddress(&p_xh, g_xh4);
    cudaGetSymbolAddress(&p_wb, g_wb4);
    cudaGetSymbolAddress(&p_we, g_weff);

    auto gemm_qkv = gemm_planar<__half, false, false>;
    auto gemm_out = gemm_planar<float, true, true>;
    cudaFuncSetAttribute(gemm_qkv, cudaFuncAttributeMaxDynamicSharedMemorySize, SMEM_GEMM);
    cudaFuncSetAttribute(gemm_out, cudaFuncAttributeMaxDynamicSharedMemorySize, SMEM_GEMM);
    cudaFuncSetAttribute(attn_mma, cudaFuncAttributeMaxDynamicSharedMemorySize, ATM_SMEM);

    // setup: mask sums + zeroing + weight convert + x fp32->fp16 (one launch)
    setup_kernel<<<648 + 6144, 256>>>(mask, qkvw, (__half*)p_wb, x, (__half*)p_xh);
    // qkv 1x1 conv: M-tile 96 (576 = 6 x 96, zero padding waste)
    gemm_qkv<<<dim3(6, HW / 128, BATCH), 256, SMEM_GEMM>>>(
        (const __half*)p_xh, (const __half*)p_wb, qkvb, (__half*)p_q0, QKVC,
        CH, 0, nullptr, nullptr);
    // 3x3 depthwise (+ fused q/k sum-of-squares)
    dwconv_kernel<<<dim3(4, QKVC, BATCH), 256>>>(
        (const __half*)p_q0, dww, dwb, (__half*)p_q1);
    // channel attention scores via tensor cores (16-way split-K)
    attn_mma<<<dim3(16, BATCH * HEADS), 256, ATM_SMEM>>>((const __half*)p_q1);
    // softmax + Weff fold (one launch)
    softmax_weff<<<BATCH, 192>>>(det, smo, outw, (__half*)p_we);
    // y = (Weff @ v) * s(n) + outb : M-tile 96 (192 = 2 x 96)
    gemm_out<<<dim3(2, HW / 128, BATCH), 256, SMEM_GEMM>>>(
        (const __half*)p_q1, (const __half*)p_we, outb, y, CH,
        QKVC, 2 * CH, mask, tbp);
}

// round 17
// speedup vs baseline: 1.1862x; 1.1025x over previous
#include <cuda_runtime.h>
#include <cuda_fp16.h>
#include <math.h>
#include <stdint.h>

// Problem constants
#define BATCH 8
#define CH    192
#define QKVC  576
#define HW    16384
#define HEADS 4
#define CPH   48

// ---------------- scratch (static device memory; no allocs) ----------------
__device__ uint4 g_q0h[(size_t)BATCH * QKVC * HW * 2 / 16];   // fp16 qkv after 1x1 (planar)
__device__ uint4 g_q1h[(size_t)BATCH * QKVC * HW * 2 / 16];   // fp16 qkv after dw (planar)
__device__ float g_sumsq[BATCH * 2 * CH];
__device__ float g_S[BATCH * HEADS * CPH * CPH];
__device__ float g_masksum[BATCH];
__device__ uint4 g_xh4[(size_t)BATCH * CH * HW * 2 / 16];     // [B][192][HW] fp16 planar
__device__ uint4 g_wb4[(size_t)(QKVC + 64) * CH * 2 / 16];    // [576(+pad)][192] fp16
__device__ uint4 g_weff[(size_t)BATCH * 256 * CH * 2 / 16];   // [B][192(+pad)][192] fp16

// ---------------- helpers ----------------
__device__ __forceinline__ uint32_t smem_u32(const void* p) {
    uint32_t a;
    asm("{ .reg .u64 t; cvta.to.shared.u64 t, %1; cvt.u32.u64 %0, t; }" : "=r"(a) : "l"(p));
    return a;
}
#define SWZ(off) ((off) ^ (((off) >> 3) & 0x70))

__device__ __forceinline__ void cp16(uint32_t dst, const void* src, int srcsz) {
    asm volatile("cp.async.cg.shared.global [%0], [%1], 16, %2;"
                 :: "r"(dst), "l"(src), "r"(srcsz) : "memory");
}
#define CP_COMMIT() asm volatile("cp.async.commit_group;" ::: "memory")

#define LDSM4(r0, r1, r2, r3, addr)                                            \
    asm volatile("ldmatrix.sync.aligned.m8n8.x4.shared.b16 {%0,%1,%2,%3}, [%4];" \
                 : "=r"(r0), "=r"(r1), "=r"(r2), "=r"(r3) : "r"(addr))

#define LDSM4T(r0, r1, r2, r3, addr)                                           \
    asm volatile("ldmatrix.sync.aligned.m8n8.x4.trans.shared.b16 {%0,%1,%2,%3}, [%4];" \
                 : "=r"(r0), "=r"(r1), "=r"(r2), "=r"(r3) : "r"(addr))

#define MMA16816(c, a, b0, b1)                                                 \
    asm volatile("mma.sync.aligned.m16n8k16.row.col.f32.f16.f16.f32 "          \
                 "{%0,%1,%2,%3},{%4,%5,%6,%7},{%8,%9},{%0,%1,%2,%3};"          \
                 : "+f"((c)[0]), "+f"((c)[1]), "+f"((c)[2]), "+f"((c)[3])      \
                 : "r"((a)[0]), "r"((a)[1]), "r"((a)[2]), "r"((a)[3]),         \
                   "r"(b0), "r"(b1))

// ---------------- setup: mask sums, zeroing, weight convert, x fp32->fp16 --
__global__ void __launch_bounds__(256) setup_kernel(const float* __restrict__ mask,
                                                    const float* __restrict__ qkvw,
                                                    __half* __restrict__ Wb,
                                                    const float* __restrict__ X,
                                                    __half* __restrict__ Xh) {
    const int bid = blockIdx.x, t = threadIdx.x;
    if (bid >= 648) {
        const size_t total4 = (size_t)BATCH * CH * HW / 4;
        for (size_t i = (size_t)(bid - 648) * 256 + t; i < total4; i += (size_t)6144 * 256) {
            float4 v = ((const float4*)X)[i];
            __half2 lo = __floats2half2_rn(v.x, v.y);
            __half2 hi = __floats2half2_rn(v.z, v.w);
            uint2 o;
            o.x = *(uint32_t*)&lo;
            o.y = *(uint32_t*)&hi;
            ((uint2*)Xh)[i] = o;
        }
    } else if (bid < 8) {
        const int b = bid;
        const float4* m4 = (const float4*)(mask + (size_t)b * HW);
        float s = 0.f;
        for (int i = t; i < HW / 4; i += 256) {
            float4 v = m4[i];
            s += v.x + v.y + v.z + v.w;
        }
#pragma unroll
        for (int o = 16; o > 0; o >>= 1) s += __shfl_xor_sync(0xFFFFFFFFu, s, o);
        __shared__ float red[8];
        if ((t & 31) == 0) red[t >> 5] = s;
        __syncthreads();
        if (t == 0) {
            float tot = 0.f;
#pragma unroll
            for (int i = 0; i < 8; i++) tot += red[i];
            g_masksum[b] = tot;
        }
    } else if (bid < 72) {
        const int idx = (bid - 8) * 256 + t;
        for (int i = idx; i < BATCH * HEADS * CPH * CPH; i += 64 * 256) g_S[i] = 0.f;
        for (int i = idx; i < BATCH * 2 * CH; i += 64 * 256) g_sumsq[i] = 0.f;
    } else {
        const int m = bid - 72;
        if (t < CH)
            Wb[(size_t)m * CH + t] = __float2half_rn(qkvw[(size_t)m * CH + t]);
    }
}

// ---------------- unified planar-B fp16 GEMM via mma.sync, M-tile 96 -------
#define AC_BYTES 12288
#define SM_VB (3 * AC_BYTES)
#define VB_ROW 272
#define VB_BYTES (64 * VB_ROW)
#define SMEM_GEMM (1024 + SM_VB + 2 * VB_BYTES)

template <typename OT, bool SCALE, bool ABATCH>
__global__ void __launch_bounds__(256, 2)
gemm_planar(const __half* __restrict__ Ball, const __half* __restrict__ A,
            const float* __restrict__ bias, OT* __restrict__ Y, int Mtot,
            int chanPB, int chanOff,
            const float* __restrict__ mask, const float* __restrict__ tbp) {
    extern __shared__ __align__(16) char smraw[];
    uint32_t sbr = smem_u32(smraw);
    uint32_t sb = (sbr + 1023) & ~1023u;
    const int t = threadIdx.x;
    const int warp = t >> 5, lane = t & 31;
    const int wm = warp >> 2, wn = warp & 3;      // warp tile m48 x n32
    const int b = blockIdx.z;
    const int M0 = blockIdx.x * 96;
    const int N0 = blockIdx.y * 128;
    const __half* vbase = Ball + (size_t)(b * chanPB + chanOff) * HW;
    const __half* Ab = A + (ABATCH ? (size_t)b * 256 * CH : 0);

    // A: 3 chunks of [96 m][64 k] -> 2304 16B units, 9 per thread
#pragma unroll
    for (int i = 0; i < 9; i++) {
        int u = t + i * 256;
        int ca = u / 768, v = u - ca * 768;
        int row = v >> 3, q = v & 7;
        const void* src = Ab + (size_t)(M0 + row) * CH + ca * 64 + q * 8;
        cp16(sb + ca * AC_BYTES + SWZ(row * 128 + q * 16), src,
             (M0 + row < Mtot) ? 16 : 0);
    }
#define VB_LOAD(ca) do {                                                           \
        uint32_t _dst = sb + SM_VB + (uint32_t)((ca) & 1) * VB_BYTES;              \
        _Pragma("unroll")                                                          \
        for (int _i = 0; _i < 4; _i++) {                                           \
            int _u = t + _i * 256;                                                 \
            int _kr = _u >> 4, _q = _u & 15;                                       \
            cp16(_dst + _kr * VB_ROW + _q * 16,                                    \
                 vbase + (size_t)((ca) * 64 + _kr) * HW + N0 + _q * 8, 16);        \
        }                                                                          \
        CP_COMMIT();                                                               \
    } while (0)

    VB_LOAD(0);
    VB_LOAD(1);

    float acc[3][4][4];
#pragma unroll
    for (int i = 0; i < 3; i++)
#pragma unroll
        for (int j = 0; j < 4; j++)
#pragma unroll
            for (int k = 0; k < 4; k++) acc[i][j][k] = 0.f;

    for (int bi = 0; bi < 3; bi++) {
        if (bi < 2) asm volatile("cp.async.wait_group 1;" ::: "memory");
        else        asm volatile("cp.async.wait_group 0;" ::: "memory");
        __syncthreads();

        const uint32_t abuf = sb + (uint32_t)bi * AC_BYTES;
        const uint32_t vbuf = sb + SM_VB + (uint32_t)(bi & 1) * VB_BYTES;
#pragma unroll
        for (int kk = 0; kk < 4; kk++) {
            uint32_t af[3][4];
#pragma unroll
            for (int mf = 0; mf < 3; mf++) {
                int row = wm * 48 + mf * 16 + (lane & 7) + ((lane & 8) ? 8 : 0);
                int cb = kk * 32 + ((lane & 16) ? 16 : 0);
                LDSM4(af[mf][0], af[mf][1], af[mf][2], af[mf][3],
                      abuf + SWZ(row * 128 + cb));
            }
#pragma unroll
            for (int nf2 = 0; nf2 < 2; nf2++) {
                int krow = kk * 16 + (lane & 7) + ((lane & 8) ? 8 : 0);
                int ncol = wn * 32 + nf2 * 16 + ((lane & 16) ? 8 : 0);
                uint32_t b0, b1, b2, b3;
                LDSM4T(b0, b1, b2, b3, vbuf + krow * VB_ROW + ncol * 2);
#pragma unroll
                for (int mf = 0; mf < 3; mf++) {
                    MMA16816(acc[mf][nf2 * 2 + 0], af[mf], b0, b1);
                    MMA16816(acc[mf][nf2 * 2 + 1], af[mf], b2, b3);
                }
            }
        }
        __syncthreads();
        if (bi + 2 < 3) VB_LOAD(bi + 2);
    }
#undef VB_LOAD

    const int g = lane >> 2, tg = lane & 3;
    const int nbase = N0 + wn * 32 + tg * 2;
    float2 sp[4];
    if (SCALE) {
        const float tb = fminf(fmaxf(*tbp, 0.1f), 0.5f);
        const float* mrow = mask + (size_t)b * HW;
#pragma unroll
        for (int nf = 0; nf < 4; nf++) {
            sp[nf].x = 1.f + tb * mrow[nbase + nf * 8];
            sp[nf].y = 1.f + tb * mrow[nbase + nf * 8 + 1];
        }
    }
#pragma unroll
    for (int mf = 0; mf < 3; mf++) {
#pragma unroll
        for (int half = 0; half < 2; half++) {
            int m = M0 + wm * 48 + mf * 16 + g + half * 8;
            if (m < Mtot) {
                float bs = bias[m];
                OT* yrow = Y + ((size_t)b * Mtot + m) * HW + nbase;
#pragma unroll
                for (int nf = 0; nf < 4; nf++) {
                    float v0 = acc[mf][nf][half * 2 + 0];
                    float v1 = acc[mf][nf][half * 2 + 1];
                    if (SCALE) { v0 = v0 * sp[nf].x; v1 = v1 * sp[nf].y; }
                    v0 += bs; v1 += bs;
                    if constexpr (sizeof(OT) == 4)
                        *(float2*)(yrow + nf * 8) = make_float2(v0, v1);
                    else
                        *(__half2*)(yrow + nf * 8) = __floats2half2_rn(v0, v1);
                }
            }
        }
    }
}

// ---------------- 3x3 depthwise conv (groups=576), fp16 smem tile ----------
// Tile kept in fp16 (34 x 136 halves): fill = raw uint4 copy (no convert),
// compute converts to fp32 in registers -> bitwise-identical results.
__global__ void __launch_bounds__(256) dwconv_kernel(const __half* __restrict__ in,
                                                     const float* __restrict__ w,
                                                     const float* __restrict__ bias,
                                                     __half* __restrict__ out) {
    const int b = blockIdx.z, ch = blockIdx.y;
    const int t = threadIdx.x;
    const int r0 = blockIdx.x * 32;
    __shared__ __align__(16) __half sm[34][136];   // 272B rows, 16B-aligned
    const __half* src = in + ((size_t)b * QKVC + ch) * HW;

#pragma unroll
    for (int i = 0; i < 3; i++) {
        int idx = t + i * 256;
        if (idx < 544) {                           // 34 rows x 16 uint4
            int rr = idx >> 4, c8 = (idx & 15) * 8;
            int gr = r0 - 1 + rr;
            uint4 v = make_uint4(0, 0, 0, 0);
            if (gr >= 0 && gr < 128) v = *(const uint4*)(src + gr * 128 + c8);
            *(uint4*)&sm[rr][c8] = v;
        }
    }
    float wv[9];
#pragma unroll
    for (int i = 0; i < 9; i++) wv[i] = w[ch * 9 + i];
    const float bsv = bias[ch];
    __syncthreads();

    const int lr = (t >> 4) * 2;                   // output row pair within tile
    const int xo = (t & 15) * 8;
    // R[dy][j] = fp32 of logical column xo-1+j (j = 0..9)
    float R[4][10];
#pragma unroll
    for (int dy = 0; dy < 4; dy++) {
        const __half* row = sm[lr + dy];
        R[dy][0] = (xo > 0) ? __half2float(row[xo - 1]) : 0.f;
        uint4 vb = *(const uint4*)&row[xo];        // 8 center halves
        const __half2* h2 = (const __half2*)&vb;
#pragma unroll
        for (int p = 0; p < 4; p++) {
            float2 f = __half22float2(h2[p]);
            R[dy][1 + p * 2] = f.x;
            R[dy][2 + p * 2] = f.y;
        }
        R[dy][9] = (xo < 120) ? __half2float(row[xo + 8]) : 0.f;
    }
    float ss = 0.f;
#pragma unroll
    for (int rr2 = 0; rr2 < 2; rr2++) {
        float o[8];
#pragma unroll
        for (int i = 0; i < 8; i++) {
            float a = bsv;
#pragma unroll
            for (int dy = 0; dy < 3; dy++)
                a += wv[dy * 3 + 0] * R[rr2 + dy][i] +
                     wv[dy * 3 + 1] * R[rr2 + dy][i + 1] +
                     wv[dy * 3 + 2] * R[rr2 + dy][i + 2];
            o[i] = a; ss += a * a;
        }
        __align__(16) __half oh[8];
#pragma unroll
        for (int i = 0; i < 8; i++) oh[i] = __float2half_rn(o[i]);
        *(uint4*)(out + ((size_t)b * QKVC + ch) * HW + (r0 + lr + rr2) * 128 + xo) =
            *(const uint4*)oh;
    }

    if (ch < 2 * CH) {
#pragma unroll
        for (int off = 16; off > 0; off >>= 1)
            ss += __shfl_xor_sync(0xFFFFFFFFu, ss, off);
        if ((t & 31) == 0) atomicAdd(&g_sumsq[b * 2 * CH + ch], ss);
    }
}

// ---------------- attention scores via mma.sync: S[bh] += q·k^T (16-way split)
#define ATM_SMEM (1024 + 2 * 16384)

__global__ void __launch_bounds__(256) attn_mma(const __half* __restrict__ qkv) {
    extern __shared__ __align__(16) char atraw[];
    uint32_t sbr = smem_u32(atraw);
    uint32_t sb = (sbr + 1023) & ~1023u;
    char* smc = atraw + (sb - sbr);
    const int bh = blockIdx.y, b = bh >> 2, h = bh & 3;
    const int t = threadIdx.x;
    const int warp = t >> 5, lane = t & 31;
    const int wm = warp >> 2, wn = warp & 3;      // warp tile m32 x n16
    const __half* qbase = qkv + ((size_t)b * QKVC + h * CPH) * HW;
    const __half* kbase = qbase + (size_t)CH * HW;
    const int n0 = blockIdx.x * 1024;             // 16 iterations of k64

    // zero pad rows 48..63 of q and k regions in BOTH buffers (once)
    {
#pragma unroll
        for (int i = 0; i < 2; i++) {
            int u = t + i * 256;
            int reg = u >> 7, off = (u & 127) * 16;
            uint32_t base = (uint32_t)(reg & 1) * 8192 + (uint32_t)(reg >> 1) * 16384;
            *(uint4*)(smc + base + 6144 + off) = make_uint4(0, 0, 0, 0);
        }
    }

#define ATM_LOAD(it) do {                                                          \
        const int _nw = n0 + (it) * 64;                                            \
        _Pragma("unroll")                                                          \
        for (int _i = 0; _i < 3; _i++) {                                           \
            int _u = t + _i * 256;                                                 \
            int _isK = _u >= 384;                                                  \
            int _v = _isK ? (_u - 384) : _u;                                       \
            int _row = _v >> 3, _q8 = _v & 7;                                      \
            const __half* _src = (_isK ? kbase : qbase) + (size_t)_row * HW + _nw + _q8 * 8; \
            cp16(sb + (uint32_t)((it) & 1) * 16384 + (_isK ? 8192 : 0) +           \
                     SWZ(_row * 128 + _q8 * 16),                                   \
                 _src, 16);                                                        \
        }                                                                          \
        CP_COMMIT();                                                               \
    } while (0)

    ATM_LOAD(0);
    ATM_LOAD(1);

    float acc[2][2][4];
#pragma unroll
    for (int i = 0; i < 2; i++)
#pragma unroll
        for (int j = 0; j < 2; j++)
#pragma unroll
            for (int k = 0; k < 4; k++) acc[i][j][k] = 0.f;

    for (int bi = 0; bi < 16; bi++) {
        if (bi < 15) asm volatile("cp.async.wait_group 1;" ::: "memory");
        else         asm volatile("cp.async.wait_group 0;" ::: "memory");
        __syncthreads();
        const uint32_t qbuf = sb + (uint32_t)(bi & 1) * 16384;
        const uint32_t kbuf = qbuf + 8192;
#pragma unroll
        for (int kk = 0; kk < 4; kk++) {
            uint32_t af[2][4];
#pragma unroll
            for (int mf = 0; mf < 2; mf++) {
                int row = wm * 32 + mf * 16 + (lane & 7) + ((lane & 8) ? 8 : 0);
                int cb = kk * 32 + ((lane & 16) ? 16 : 0);
                LDSM4(af[mf][0], af[mf][1], af[mf][2], af[mf][3],
                      qbuf + SWZ(row * 128 + cb));
            }
            int rowb = wn * 16 + (lane & 7) + ((lane & 16) ? 8 : 0);
            int cbb = kk * 32 + ((lane & 8) ? 16 : 0);
            uint32_t b0, b1, b2, b3;
            LDSM4(b0, b1, b2, b3, kbuf + SWZ(rowb * 128 + cbb));
#pragma unroll
            for (int mf = 0; mf < 2; mf++) {
                MMA16816(acc[mf][0], af[mf], b0, b1);
                MMA16816(acc[mf][1], af[mf], b2, b3);
            }
        }
        __syncthreads();
        if (bi + 2 < 16) ATM_LOAD(bi + 2);
    }
#undef ATM_LOAD

    float* Sb = g_S + (size_t)bh * CPH * CPH;
    const int g = lane >> 2, tg = lane & 3;
#pragma unroll
    for (int mf = 0; mf < 2; mf++)
#pragma unroll
        for (int half = 0; half < 2; half++) {
            int m = wm * 32 + mf * 16 + g + half * 8;
            if (m < CPH) {
#pragma unroll
                for (int nf = 0; nf < 2; nf++)
#pragma unroll
                    for (int j = 0; j < 2; j++) {
                        int d = wn * 16 + nf * 8 + tg * 2 + j;
                        if (d < CPH)
                            atomicAdd(&Sb[m * CPH + d], acc[mf][nf][half * 2 + j]);
                    }
            }
        }
}

// ---------------- fused softmax (norm+temp) + Weff = W2 · blockdiag(A) -----
__global__ void __launch_bounds__(192) softmax_weff(const float* __restrict__ det,
                                                    const float* __restrict__ smo,
                                                    const float* __restrict__ W2,
                                                    __half* __restrict__ Weff) {
    const int b = blockIdx.x, t = threadIdx.x;   // 192 threads
    __shared__ float As[HEADS * CPH * CPH];

    {
        const int h = t / CPH, r = t % CPH;
        const float tl = g_masksum[b] / (float)HW;
        const float temp = det[h] * tl + smo[h] * (1.f - tl);
        const float invq = 1.f / fmaxf(sqrtf(g_sumsq[b * 2 * CH + h * CPH + r]), 1e-12f);
        const float* Srow = g_S + ((size_t)(b * HEADS + h) * CPH + r) * CPH;
        float vals[CPH];
        float mx = -1e30f;
#pragma unroll
        for (int d = 0; d < CPH; d++) {
            float invk = 1.f / fmaxf(sqrtf(g_sumsq[b * 2 * CH + CH + h * CPH + d]), 1e-12f);
            float v = Srow[d] * invq * invk * temp;
            vals[d] = v;
            mx = fmaxf(mx, v);
        }
        float sum = 0.f;
#pragma unroll
        for (int d = 0; d < CPH; d++) { vals[d] = expf(vals[d] - mx); sum += vals[d]; }
        float inv = 1.f / sum;
        float* Arow = As + (h * CPH + r) * CPH;
#pragma unroll
        for (int d = 0; d < CPH; d++) Arow[d] = vals[d] * inv;
    }
    __syncthreads();

    const int m = t;
    __half* wrow_out = Weff + ((size_t)b * 256 + m) * CH;
#pragma unroll
    for (int h = 0; h < HEADS; h++) {
        float wr[CPH];
#pragma unroll
        for (int cc = 0; cc < CPH; cc++) wr[cc] = W2[(size_t)m * CH + h * CPH + cc];
        const float* Ah = As + h * CPH * CPH;
        for (int d0 = 0; d0 < CPH; d0 += 4) {
            float s0 = 0.f, s1 = 0.f, s2 = 0.f, s3 = 0.f;
#pragma unroll
            for (int cc = 0; cc < CPH; cc++) {
                float w = wr[cc];
                const float* ar = Ah + cc * CPH + d0;
                s0 += w * ar[0]; s1 += w * ar[1];
                s2 += w * ar[2]; s3 += w * ar[3];
            }
            wrow_out[h * CPH + d0 + 0] = __float2half_rn(s0);
            wrow_out[h * CPH + d0 + 1] = __float2half_rn(s1);
            wrow_out[h * CPH + d0 + 2] = __float2half_rn(s2);
            wrow_out[h * CPH + d0 + 3] = __float2half_rn(s3);
        }
    }
}

// ---------------- host launcher ----------------
extern "C" void kernel_launch(void* const* d_in, const int* in_sizes, int n_in,
                              void* d_out, int out_size) {
    const float* x    = (const float*)d_in[0];
    const float* mask = (const float*)d_in[1];
    const float* qkvw = (const float*)d_in[2];
    const float* qkvb = (const float*)d_in[3];
    const float* dww  = (const float*)d_in[4];
    const float* dwb  = (const float*)d_in[5];
    const float* outw = (const float*)d_in[6];
    const float* outb = (const float*)d_in[7];
    const float* det  = (const float*)d_in[8];
    const float* smo  = (const float*)d_in[9];
    const float* tbp  = (const float*)d_in[10];
    float* y = (float*)d_out;

    void *p_q0 = nullptr, *p_q1 = nullptr, *p_xh = nullptr, *p_wb = nullptr, *p_we = nullptr;
    cudaGetSymbolAddress(&p_q0, g_q0h);
    cudaGetSymbolAddress(&p_q1, g_q1h);
    cudaGetSymbolAddress(&p_xh, g_xh4);
    cudaGetSymbolAddress(&p_wb, g_wb4);
    cudaGetSymbolAddress(&p_we, g_weff);

    auto gemm_qkv = gemm_planar<__half, false, false>;
    auto gemm_out = gemm_planar<float, true, true>;
    cudaFuncSetAttribute(gemm_qkv, cudaFuncAttributeMaxDynamicSharedMemorySize, SMEM_GEMM);
    cudaFuncSetAttribute(gemm_out, cudaFuncAttributeMaxDynamicSharedMemorySize, SMEM_GEMM);
    cudaFuncSetAttribute(attn_mma, cudaFuncAttributeMaxDynamicSharedMemorySize, ATM_SMEM);

    // setup: mask sums + zeroing + weight convert + x fp32->fp16 (one launch)
    setup_kernel<<<648 + 6144, 256>>>(mask, qkvw, (__half*)p_wb, x, (__half*)p_xh);
    // qkv 1x1 conv: M-tile 96 (576 = 6 x 96)
    gemm_qkv<<<dim3(6, HW / 128, BATCH), 256, SMEM_GEMM>>>(
        (const __half*)p_xh, (const __half*)p_wb, qkvb, (__half*)p_q0, QKVC,
        CH, 0, nullptr, nullptr);
    // 3x3 depthwise (+ fused q/k sum-of-squares), fp16 smem tile
    dwconv_kernel<<<dim3(4, QKVC, BATCH), 256>>>(
        (const __half*)p_q0, dww, dwb, (__half*)p_q1);
    // channel attention scores via tensor cores (16-way split-K)
    attn_mma<<<dim3(16, BATCH * HEADS), 256, ATM_SMEM>>>((const __half*)p_q1);
    // softmax + Weff fold (one launch)
    softmax_weff<<<BATCH, 192>>>(det, smo, outw, (__half*)p_we);
    // y = (Weff @ v) * s(n) + outb : M-tile 96 (192 = 2 x 96)
    gemm_out<<<dim3(2, HW / 128, BATCH), 256, SMEM_GEMM>>>(
        (const __half*)p_q1, (const __half*)p_we, outb, y, CH,
        QKVC, 2 * CH, mask, tbp);
}